// round 13
// baseline (speedup 1.0000x reference)
#include <cuda_runtime.h>
#include <math.h>
#include <stdint.h>

#define TSTEPS 1024
#define BATCH  64
#define HID    512

// ---------------- scratch (static device allocations; no cudaMalloc) ----------------
__device__ float g_Zf[(size_t)TSTEPS * BATCH * 2048];   // Z fwd [t][b][4H]; later A_hi
__device__ float g_Zb[(size_t)TSTEPS * BATCH * 2048];   // Z bwd [t][b][4H]; later A_lo
__device__ float g_h1[(size_t)BATCH * TSTEPS * 1024];   // layer1 out [b][t][2H] (tf32)
__device__ float g_h2[(size_t)BATCH * TSTEPS * 1024];   // layer2 out [b][t][2H] (fp32)
__device__ float g_xr[(size_t)BATCH * TSTEPS * 512];    // tf32-rounded x
__device__ float g_hst[2][2][HID][BATCH];               // h state [dir][phase][col][b] (tf32)
__device__ unsigned int g_flags[2][64];                 // per-CTA step flags (barrier)

// transposed + tf32-rounded weights [N][K]
__device__ float g_Wt1f[2048 * 512];
__device__ float g_Wt1b[2048 * 512];
__device__ float g_Wt2f[2048 * 1024];
__device__ float g_Wt2b[2048 * 1024];
__device__ float g_Wtd [512 * 1024];
__device__ float g_WtdLo[512 * 1024];

__device__ __forceinline__ float to_tf32(float v) {
    float r; asm("cvt.rna.tf32.f32 %0, %1;" : "=f"(r) : "f"(v)); return r;
}
__device__ __forceinline__ uint32_t smem_u32(const void* p) {
    uint32_t a;
    asm("{ .reg .u64 t; cvta.to.shared.u64 t, %1; cvt.u32.u64 %0, t; }" : "=r"(a) : "l"(p));
    return a;
}
__device__ __forceinline__ float fsigm(float x) { return 1.f / (1.f + __expf(-x)); }
__device__ __forceinline__ float ftanh(float x) {
    float e = __expf(2.f * x);
    return 1.f - __fdividef(2.f, e + 1.f);
}
__device__ __forceinline__ void cp16(uint32_t dst, const void* src) {
    asm volatile("cp.async.cg.shared.global [%0], [%1], 16;" :: "r"(dst), "l"(src));
}

// =====================================================================
//  Fused prep kernel: blockIdx.y selects task.
// =====================================================================
__global__ void prep_all_kernel(
    const float* __restrict__ x,   float* __restrict__ xr,
    const float* __restrict__ W1f, float* __restrict__ Wt1f,
    const float* __restrict__ W1b, float* __restrict__ Wt1b,
    const float* __restrict__ W2f, float* __restrict__ Wt2f,
    const float* __restrict__ W2b, float* __restrict__ Wt2b,
    const float* __restrict__ Wd,  float* __restrict__ Wtd, float* __restrict__ WtdLo)
{
    const int task = blockIdx.y;
    if (task == 0) {
        const int n4 = 8388608;
        for (int i = blockIdx.x * 256 + threadIdx.x; i < n4; i += 2048 * 256) {
            float4 v = ((const float4*)x)[i];
            ((float4*)xr)[i] = make_float4(to_tf32(v.x), to_tf32(v.y),
                                           to_tf32(v.z), to_tf32(v.w));
        }
        return;
    }
    const float* W; float* Wt; float* Wlo = nullptr; int K, N;
    switch (task) {
        case 1: W = W1f; Wt = Wt1f; K = 512;  N = 2048; break;
        case 2: W = W1b; Wt = Wt1b; K = 512;  N = 2048; break;
        case 3: W = W2f; Wt = Wt2f; K = 1024; N = 2048; break;
        case 4: W = W2b; Wt = Wt2b; K = 1024; N = 2048; break;
        default: W = Wd; Wt = Wtd; Wlo = WtdLo; K = 1024; N = 512; break;
    }
    const int nkb = K / 32;
    const int total = nkb * (N / 32);
    const int bx = blockIdx.x;
    if (bx >= total) return;
    __shared__ float tile[32][33];
    const int kb = (bx % nkb) * 32, nb = (bx / nkb) * 32;
    const int tx = threadIdx.x & 31, ty = threadIdx.x >> 5;
#pragma unroll
    for (int i = ty; i < 32; i += 8)
        tile[i][tx] = W[(size_t)(kb + i) * N + nb + tx];
    __syncthreads();
#pragma unroll
    for (int i = ty; i < 32; i += 8) {
        float v = tile[tx][i];
        float hi = to_tf32(v);
        Wt[(size_t)(nb + i) * K + kb + tx] = hi;
        if (Wlo) Wlo[(size_t)(nb + i) * K + kb + tx] = to_tf32(v - hi);
    }
}

// A_hi = tf32(h1+h2), A_lo = tf32((h1+h2)-A_hi)
__global__ void add_split_kernel(const float* __restrict__ a, const float* __restrict__ b,
                                 float* __restrict__ ohi, float* __restrict__ olo, int n4)
{
    int i = blockIdx.x * blockDim.x + threadIdx.x;
    if (i < n4) {
        float4 va = ((const float4*)a)[i];
        float4 vb = ((const float4*)b)[i];
        float s0 = va.x + vb.x, s1 = va.y + vb.y, s2 = va.z + vb.z, s3 = va.w + vb.w;
        float h0 = to_tf32(s0), h1v = to_tf32(s1), h2v = to_tf32(s2), h3 = to_tf32(s3);
        ((float4*)ohi)[i] = make_float4(h0, h1v, h2v, h3);
        ((float4*)olo)[i] = make_float4(to_tf32(s0 - h0), to_tf32(s1 - h1v),
                                        to_tf32(s2 - h2v), to_tf32(s3 - h3));
    }
}

// =====================================================================
//  TF32 mma.sync GEMM (validated R4):  C = A @ Bt^T (+bias | +=)
// =====================================================================
#define ABUF 4608   // 128*36 floats per buffer

template <int SCATTER, int ACCUM>
__global__ void __launch_bounds__(256, 2)
mma_gemm_kernel(const float* __restrict__ A, const float* __restrict__ Bt,
                const float* __restrict__ bias, float* __restrict__ C, int K, int N)
{
    extern __shared__ float smf[];
    const int tid = threadIdx.x;
    const int wid = tid >> 5, lane = tid & 31;
    const int warp_m = wid & 1, warp_n = wid >> 1;
    const size_t rowBase = (size_t)blockIdx.y * 128;
    const size_t colBase = (size_t)blockIdx.x * 128;
    const uint32_t smbase = smem_u32(smf);
    const int NS = K >> 5;

    float acc[4][4][4];
#pragma unroll
    for (int mi = 0; mi < 4; ++mi)
#pragma unroll
        for (int ni = 0; ni < 4; ++ni)
#pragma unroll
            for (int r = 0; r < 4; ++r) acc[mi][ni][r] = 0.f;

    auto cp_tile = [&](int s, int p) {
        const int kt = s << 5;
#pragma unroll
        for (int i = 0; i < 4; ++i) {
            int idx = i * 256 + tid;
            int row = idx >> 3, f4 = idx & 7;
            uint32_t da = smbase + (uint32_t)((p * ABUF + row * 36 + f4 * 4) << 2);
            cp16(da, A + (rowBase + row) * K + kt + f4 * 4);
            uint32_t db = smbase + (uint32_t)(((2 * ABUF) + p * ABUF + row * 36 + f4 * 4) << 2);
            cp16(db, Bt + (colBase + row) * K + kt + f4 * 4);
        }
        asm volatile("cp.async.commit_group;");
    };

    cp_tile(0, 0);
    cp_tile(1, 1);

    const int g = lane >> 2, c = lane & 3;
    const int ar0 = warp_m * 64 + g;
    const int bn0 = warp_n * 32 + g;

    for (int s = 0; s < NS; ++s) {
        const int p = s & 1;
        if (s + 1 < NS) asm volatile("cp.async.wait_group 1;");
        else            asm volatile("cp.async.wait_group 0;");
        __syncthreads();

        const float* Ab = smf + p * ABUF;
        const float* Bb = smf + 2 * ABUF + p * ABUF;

#pragma unroll
        for (int k8 = 0; k8 < 4; ++k8) {
            const int kc = k8 * 8 + c;
            uint32_t a[4][4], b[4][2];
#pragma unroll
            for (int mi = 0; mi < 4; ++mi) {
                const float* base = Ab + (ar0 + mi * 16) * 36 + kc;
                a[mi][0] = __float_as_uint(base[0]);
                a[mi][1] = __float_as_uint(base[8 * 36]);
                a[mi][2] = __float_as_uint(base[4]);
                a[mi][3] = __float_as_uint(base[8 * 36 + 4]);
            }
#pragma unroll
            for (int ni = 0; ni < 4; ++ni) {
                const float* base = Bb + (bn0 + ni * 8) * 36 + kc;
                b[ni][0] = __float_as_uint(base[0]);
                b[ni][1] = __float_as_uint(base[4]);
            }
#pragma unroll
            for (int mi = 0; mi < 4; ++mi)
#pragma unroll
                for (int ni = 0; ni < 4; ++ni)
                    asm volatile(
                        "mma.sync.aligned.m16n8k8.row.col.f32.tf32.tf32.f32 "
                        "{%0,%1,%2,%3}, {%4,%5,%6,%7}, {%8,%9}, {%0,%1,%2,%3};"
                        : "+f"(acc[mi][ni][0]), "+f"(acc[mi][ni][1]),
                          "+f"(acc[mi][ni][2]), "+f"(acc[mi][ni][3])
                        : "r"(a[mi][0]), "r"(a[mi][1]), "r"(a[mi][2]), "r"(a[mi][3]),
                          "r"(b[ni][0]), "r"(b[ni][1]));
        }
        __syncthreads();
        if (s + 2 < NS) cp_tile(s + 2, p);
    }

    const int c2 = (lane & 3) * 2;
#pragma unroll
    for (int mi = 0; mi < 4; ++mi) {
        size_t r0 = rowBase + warp_m * 64 + mi * 16 + g;
        size_t r8 = r0 + 8;
        size_t off0, off8;
        if (SCATTER) {
            off0 = (((r0 & 1023) << 6) + (r0 >> 10)) * (size_t)N;
            off8 = (((r8 & 1023) << 6) + (r8 >> 10)) * (size_t)N;
        } else {
            off0 = r0 * (size_t)N;
            off8 = r8 * (size_t)N;
        }
#pragma unroll
        for (int ni = 0; ni < 4; ++ni) {
            size_t col = colBase + warp_n * 32 + ni * 8 + c2;
            float2 v0, v1;
            if (ACCUM) {
                float2 o0 = *(const float2*)&C[off0 + col];
                float2 o1 = *(const float2*)&C[off8 + col];
                v0 = make_float2(acc[mi][ni][0] + o0.x, acc[mi][ni][1] + o0.y);
                v1 = make_float2(acc[mi][ni][2] + o1.x, acc[mi][ni][3] + o1.y);
            } else {
                float2 bv = *(const float2*)&bias[col];
                v0 = make_float2(acc[mi][ni][0] + bv.x, acc[mi][ni][1] + bv.y);
                v1 = make_float2(acc[mi][ni][2] + bv.x, acc[mi][ni][3] + bv.y);
            }
            *(float2*)&C[off0 + col] = v0;
            *(float2*)&C[off8 + col] = v1;
        }
    }
}

// =====================================================================
//  Persistent bidirectional LSTM layer — tensor-core recurrence.
//  R13: flag-array grid barrier (parallel arrive/poll, no atomic
//  serialization) + two-stage staging (MMA overlaps 2nd half flight).
// =====================================================================
__device__ __forceinline__ void bar_arrive(int dir, int jb, unsigned int val)
{
    __threadfence();
    __syncthreads();
    if (threadIdx.x == 0)
        *((volatile unsigned int*)&g_flags[dir][jb]) = val;
}
__device__ __forceinline__ void bar_wait(int dir, unsigned int target)
{
    if (threadIdx.x < 64)
        while (*((volatile unsigned int*)&g_flags[dir][threadIdx.x]) < target) { }
    __syncthreads();
}

#define LSTM_SMEM ((36864 + 4 * 32 * 66) * 4)

template <int ROUND>
__global__ void __launch_bounds__(256, 1)
lstm_mma_kernel(const float* __restrict__ Zf, const float* __restrict__ Zb,
                const float* __restrict__ Uf, const float* __restrict__ Ub,
                float* __restrict__ hout)
{
    extern __shared__ float sm[];
    float* hs   = sm;           // [4 ks][128 k][72]  (pad-72)
    float* zred = sm + 36864;   // [4 ks][32 l][66]

    const int tid = threadIdx.x;
    const int w = tid >> 5, lane = tid & 31;
    const int g = lane >> 2, c = lane & 3;
    const int ks = w >> 1, mg = w & 1;
    const int dir = blockIdx.x >> 6;
    const int jb  = blockIdx.x & 63;
    const float* U = dir ? Ub : Uf;
    const float* Z = dir ? Zb : Zf;
    float* hst0 = &g_hst[dir][0][0][0];
    float* hst1 = &g_hst[dir][1][0][0];

    // ---- one-time: U A-fragments (tf32-rounded), registers ----
    float uhi[16][4];
    {
        const int l0 = mg * 16 + g, l1 = l0 + 8;
        const int gc0 = (l0 >> 3) * 512 + jb * 8 + (l0 & 7);
        const int gc1 = (l1 >> 3) * 512 + jb * 8 + (l1 & 7);
#pragma unroll
        for (int kk = 0; kk < 16; ++kk) {
            int k = ks * 128 + kk * 8;
            uhi[kk][0] = to_tf32(U[(size_t)(k + c) * 2048 + gc0]);
            uhi[kk][1] = to_tf32(U[(size_t)(k + c) * 2048 + gc1]);
            uhi[kk][2] = to_tf32(U[(size_t)(k + c + 4) * 2048 + gc0]);
            uhi[kk][3] = to_tf32(U[(size_t)(k + c + 4) * 2048 + gc1]);
        }
    }

    // zero own cols of phase-0 state
    for (int i = tid; i < 512; i += 256) hst0[jb * 8 * 64 + i] = 0.f;
    bar_arrive(dir, jb, 1u);
    bar_wait(dir, 1u);

    const int eb = tid >> 2;
    const int q0 = (tid & 3) * 2;
    float cst0 = 0.f, cst1 = 0.f;
    const int pt = tid & 63;
    float* hsP = hs + ks * 9216;
    const uint32_t hsPb = smem_u32(hsP);

    // prologue Z prefetch for s=0
    float2 zi2, zf2, zg2, zo2;
    {
        int t0 = dir ? (TSTEPS - 1) : 0;
        const float* Zt = Z + ((size_t)t0 * 64 + eb) * 2048 + jb * 8 + q0;
        zi2 = *(const float2*)(Zt + 0);
        zf2 = *(const float2*)(Zt + 512);
        zg2 = *(const float2*)(Zt + 1024);
        zo2 = *(const float2*)(Zt + 1536);
    }

    for (int s = 0; s < TSTEPS; ++s) {
        const int t = dir ? (TSTEPS - 1 - s) : s;
        const float* hsrc = (s & 1) ? hst1 : hst0;
        float* hdst = (s & 1) ? hst0 : hst1;

        // ---- two-stage staging: [col][b] -> smem [k][72] ----
        // i<16 stages k rows 0..63 (kk 0..7); i>=16 stages 64..127.
        {
            const float4* src = (const float4*)(hsrc + ks * 8192);
#pragma unroll
            for (int i = 0; i < 16; ++i) {
                int idx = i * 64 + pt;
                int kl = idx >> 4, q4 = idx & 15;
                cp16(hsPb + (uint32_t)((kl * 72 + q4 * 4) << 2), src + idx);
            }
            asm volatile("cp.async.commit_group;");
#pragma unroll
            for (int i = 16; i < 32; ++i) {
                int idx = i * 64 + pt;
                int kl = idx >> 4, q4 = idx & 15;
                cp16(hsPb + (uint32_t)((kl * 72 + q4 * 4) << 2), src + idx);
            }
            asm volatile("cp.async.commit_group;");
        }

        float acc[8][4];
#pragma unroll
        for (int nt = 0; nt < 8; ++nt)
#pragma unroll
            for (int r = 0; r < 4; ++r) acc[nt][r] = 0.f;

        // first half ready -> MMA kk 0..7 overlaps second half flight
        asm volatile("cp.async.wait_group 1;");
        asm volatile("bar.sync %0, %1;" :: "r"(1 + ks), "r"(64) : "memory");

#pragma unroll
        for (int kk = 0; kk < 8; ++kk) {
            uint32_t ah0 = __float_as_uint(uhi[kk][0]), ah1 = __float_as_uint(uhi[kk][1]);
            uint32_t ah2 = __float_as_uint(uhi[kk][2]), ah3 = __float_as_uint(uhi[kk][3]);
            const uint32_t* rowA = (const uint32_t*)(hsP + (kk * 8 + c) * 72);
            const uint32_t* rowB = rowA + 4 * 72;
#pragma unroll
            for (int nt = 0; nt < 8; ++nt) {
                uint32_t b0 = rowA[nt * 8 + g];
                uint32_t b1 = rowB[nt * 8 + g];
                asm volatile(
                    "mma.sync.aligned.m16n8k8.row.col.f32.tf32.tf32.f32 "
                    "{%0,%1,%2,%3}, {%4,%5,%6,%7}, {%8,%9}, {%0,%1,%2,%3};"
                    : "+f"(acc[nt][0]), "+f"(acc[nt][1]), "+f"(acc[nt][2]), "+f"(acc[nt][3])
                    : "r"(ah0), "r"(ah1), "r"(ah2), "r"(ah3),
                      "r"(b0), "r"(b1));
            }
        }

        asm volatile("cp.async.wait_group 0;");
        asm volatile("bar.sync %0, %1;" :: "r"(1 + ks), "r"(64) : "memory");

#pragma unroll
        for (int kk = 8; kk < 16; ++kk) {
            uint32_t ah0 = __float_as_uint(uhi[kk][0]), ah1 = __float_as_uint(uhi[kk][1]);
            uint32_t ah2 = __float_as_uint(uhi[kk][2]), ah3 = __float_as_uint(uhi[kk][3]);
            const uint32_t* rowA = (const uint32_t*)(hsP + (kk * 8 + c) * 72);
            const uint32_t* rowB = rowA + 4 * 72;
#pragma unroll
            for (int nt = 0; nt < 8; ++nt) {
                uint32_t b0 = rowA[nt * 8 + g];
                uint32_t b1 = rowB[nt * 8 + g];
                asm volatile(
                    "mma.sync.aligned.m16n8k8.row.col.f32.tf32.tf32.f32 "
                    "{%0,%1,%2,%3}, {%4,%5,%6,%7}, {%8,%9}, {%0,%1,%2,%3};"
                    : "+f"(acc[nt][0]), "+f"(acc[nt][1]), "+f"(acc[nt][2]), "+f"(acc[nt][3])
                    : "r"(ah0), "r"(ah1), "r"(ah2), "r"(ah3),
                      "r"(b0), "r"(b1));
            }
        }

        // ---- store partials: zred[ks][l][b] ----
#pragma unroll
        for (int nt = 0; nt < 8; ++nt) {
            int l0 = mg * 16 + g;
            int n0 = nt * 8 + c * 2;
            *(float2*)&zred[(ks * 32 + l0) * 66 + n0]     = make_float2(acc[nt][0], acc[nt][1]);
            *(float2*)&zred[(ks * 32 + l0 + 8) * 66 + n0] = make_float2(acc[nt][2], acc[nt][3]);
        }
        __syncthreads();

        // ---- gate epilogue ----
        float hh0, hh1;
        {
            float vi0 = zi2.x, vi1 = zi2.y, vf0 = zf2.x, vf1 = zf2.y;
            float vg0 = zg2.x, vg1 = zg2.y, vo0 = zo2.x, vo1 = zo2.y;
#pragma unroll
            for (int k = 0; k < 4; ++k) {
                vi0 += zred[(k * 32 + q0)      * 66 + eb];
                vi1 += zred[(k * 32 + q0 + 1)  * 66 + eb];
                vf0 += zred[(k * 32 + 8 + q0)  * 66 + eb];
                vf1 += zred[(k * 32 + 9 + q0)  * 66 + eb];
                vg0 += zred[(k * 32 + 16 + q0) * 66 + eb];
                vg1 += zred[(k * 32 + 17 + q0) * 66 + eb];
                vo0 += zred[(k * 32 + 24 + q0) * 66 + eb];
                vo1 += zred[(k * 32 + 25 + q0) * 66 + eb];
            }
            float ig0 = fsigm(vi0), ig1 = fsigm(vi1);
            float fg0 = fsigm(vf0), fg1 = fsigm(vf1);
            float gg0 = ftanh(vg0), gg1 = ftanh(vg1);
            float og0 = fsigm(vo0), og1 = fsigm(vo1);
            cst0 = fg0 * cst0 + ig0 * gg0;
            cst1 = fg1 * cst1 + ig1 * gg1;
            hh0 = og0 * ftanh(cst0);
            hh1 = og1 * ftanh(cst1);

            __stcg(&hdst[(jb * 8 + q0) * 64 + eb],     to_tf32(hh0));
            __stcg(&hdst[(jb * 8 + q0 + 1) * 64 + eb], to_tf32(hh1));
        }

        bar_arrive(dir, jb, (unsigned)(s + 2));

        size_t ho = ((size_t)eb * 1024 + t) * 1024 + dir * 512 + jb * 8 + q0;
        if (ROUND) {
            hout[ho]     = to_tf32(hh0);
            hout[ho + 1] = to_tf32(hh1);
        } else {
            hout[ho]     = hh0;
            hout[ho + 1] = hh1;
        }

        if (s + 1 < TSTEPS) {
            int tn = dir ? (TSTEPS - 2 - s) : (s + 1);
            const float* Zt = Z + ((size_t)tn * 64 + eb) * 2048 + jb * 8 + q0;
            zi2 = *(const float2*)(Zt + 0);
            zf2 = *(const float2*)(Zt + 512);
            zg2 = *(const float2*)(Zt + 1024);
            zo2 = *(const float2*)(Zt + 1536);
            bar_wait(dir, (unsigned)(s + 2));
        }
    }
}

__global__ void reset_bar_kernel() {
    if (threadIdx.x < 64) {
        g_flags[0][threadIdx.x] = 0u;
        g_flags[1][threadIdx.x] = 0u;
    }
}

// =====================================================================
extern "C" void kernel_launch(void* const* d_in, const int* in_sizes, int n_in,
                              void* d_out, int out_size)
{
    (void)in_sizes; (void)n_in; (void)out_size;
    const float* x   = (const float*)d_in[0];
    const float* W1f = (const float*)d_in[1];
    const float* U1f = (const float*)d_in[2];
    const float* b1f = (const float*)d_in[3];
    const float* W1b = (const float*)d_in[4];
    const float* U1b = (const float*)d_in[5];
    const float* b1b = (const float*)d_in[6];
    const float* W2f = (const float*)d_in[7];
    const float* U2f = (const float*)d_in[8];
    const float* b2f = (const float*)d_in[9];
    const float* W2b = (const float*)d_in[10];
    const float* U2b = (const float*)d_in[11];
    const float* b2b = (const float*)d_in[12];
    const float* Wd  = (const float*)d_in[13];
    const float* bd  = (const float*)d_in[14];
    float* out = (float*)d_out;

    float *Zf, *Zb, *h1, *h2, *xr;
    float *Wt1f, *Wt1b, *Wt2f, *Wt2b, *Wtd, *WtdLo;
    cudaGetSymbolAddress((void**)&Zf, g_Zf);
    cudaGetSymbolAddress((void**)&Zb, g_Zb);
    cudaGetSymbolAddress((void**)&h1, g_h1);
    cudaGetSymbolAddress((void**)&h2, g_h2);
    cudaGetSymbolAddress((void**)&xr, g_xr);
    cudaGetSymbolAddress((void**)&Wt1f, g_Wt1f);
    cudaGetSymbolAddress((void**)&Wt1b, g_Wt1b);
    cudaGetSymbolAddress((void**)&Wt2f, g_Wt2f);
    cudaGetSymbolAddress((void**)&Wt2b, g_Wt2b);
    cudaGetSymbolAddress((void**)&Wtd, g_Wtd);
    cudaGetSymbolAddress((void**)&WtdLo, g_WtdLo);

    const int GEMM_SMEM = 4 * ABUF * 4;
    cudaFuncSetAttribute(mma_gemm_kernel<0, 0>, cudaFuncAttributeMaxDynamicSharedMemorySize, GEMM_SMEM);
    cudaFuncSetAttribute(mma_gemm_kernel<0, 1>, cudaFuncAttributeMaxDynamicSharedMemorySize, GEMM_SMEM);
    cudaFuncSetAttribute(mma_gemm_kernel<1, 0>, cudaFuncAttributeMaxDynamicSharedMemorySize, GEMM_SMEM);
    cudaFuncSetAttribute(lstm_mma_kernel<0>, cudaFuncAttributeMaxDynamicSharedMemorySize, LSTM_SMEM);
    cudaFuncSetAttribute(lstm_mma_kernel<1>, cudaFuncAttributeMaxDynamicSharedMemorySize, LSTM_SMEM);

    dim3 blk(256);
    dim3 gZ(2048 / 128, 65536 / 128);
    dim3 gO(512 / 128, 65536 / 128);

    prep_all_kernel<<<dim3(2048, 6), 256>>>(x, xr, W1f, Wt1f, W1b, Wt1b,
                                            W2f, Wt2f, W2b, Wt2b, Wd, Wtd, WtdLo);
    mma_gemm_kernel<1, 0><<<gZ, blk, GEMM_SMEM>>>(xr, Wt1f, b1f, Zf, 512, 2048);
    mma_gemm_kernel<1, 0><<<gZ, blk, GEMM_SMEM>>>(xr, Wt1b, b1b, Zb, 512, 2048);
    reset_bar_kernel<<<1, 64>>>();

    // layer-1 recurrence
    lstm_mma_kernel<1><<<128, 256, LSTM_SMEM>>>(Zf, Zb, U1f, U1b, h1);

    // layer-2 input projections
    mma_gemm_kernel<1, 0><<<gZ, blk, GEMM_SMEM>>>(h1, Wt2f, b2f, Zf, 1024, 2048);
    mma_gemm_kernel<1, 0><<<gZ, blk, GEMM_SMEM>>>(h1, Wt2b, b2b, Zb, 1024, 2048);

    // layer-2 recurrence
    reset_bar_kernel<<<1, 64>>>();
    lstm_mma_kernel<0><<<128, 256, LSTM_SMEM>>>(Zf, Zb, U2f, U2b, h2);

    // dense head, 3-term split: out = (h1+h2)@Wd + bd
    add_split_kernel<<<(16777216 + 255) / 256, 256>>>(h1, h2, Zf, Zb, 16777216);
    mma_gemm_kernel<0, 0><<<gO, blk, GEMM_SMEM>>>(Zf, Wtd,   bd, out, 1024, 512);
    mma_gemm_kernel<0, 1><<<gO, blk, GEMM_SMEM>>>(Zb, Wtd,   bd, out, 1024, 512);
    mma_gemm_kernel<0, 1><<<gO, blk, GEMM_SMEM>>>(Zf, WtdLo, bd, out, 1024, 512);
}

// round 15
// speedup vs baseline: 1.2656x; 1.2656x over previous
#include <cuda_runtime.h>
#include <math.h>
#include <stdint.h>

#define TSTEPS 1024
#define BATCH  64
#define HID    512

// ---------------- scratch (static device allocations; no cudaMalloc) ----------------
__device__ float g_Zf[(size_t)TSTEPS * BATCH * 2048];   // Z fwd [t][b][4H]; later hsum
__device__ float g_Zb[(size_t)TSTEPS * BATCH * 2048];   // Z bwd [t][b][4H]
__device__ float g_h1[(size_t)BATCH * TSTEPS * 1024];   // layer1 out [b][t][2H] (tf32)
__device__ float g_h2[(size_t)BATCH * TSTEPS * 1024];   // layer2 out [b][t][2H] (fp32)
__device__ float g_xr[(size_t)BATCH * TSTEPS * 512];    // tf32-rounded x
__device__ float g_hst[2][2][HID][BATCH];               // h state [dir][phase][col][b] (tf32)
__device__ unsigned int g_bar2[64];                     // per-dir barrier counters ([0],[32])

// transposed + tf32-rounded weights [N][K]
__device__ float g_Wt1f[2048 * 512];
__device__ float g_Wt1b[2048 * 512];
__device__ float g_Wt2f[2048 * 1024];
__device__ float g_Wt2b[2048 * 1024];
__device__ float g_Wtd [512 * 1024];

__device__ __forceinline__ float to_tf32(float v) {
    float r; asm("cvt.rna.tf32.f32 %0, %1;" : "=f"(r) : "f"(v)); return r;
}
__device__ __forceinline__ uint32_t smem_u32(const void* p) {
    uint32_t a;
    asm("{ .reg .u64 t; cvta.to.shared.u64 t, %1; cvt.u32.u64 %0, t; }" : "=r"(a) : "l"(p));
    return a;
}
__device__ __forceinline__ float fsigm(float x) { return 1.f / (1.f + __expf(-x)); }
__device__ __forceinline__ float ftanh(float x) {
    float e = __expf(2.f * x);
    return 1.f - __fdividef(2.f, e + 1.f);
}
__device__ __forceinline__ void cp16(uint32_t dst, const void* src) {
    asm volatile("cp.async.cg.shared.global [%0], [%1], 16;" :: "r"(dst), "l"(src));
}

// =====================================================================
//  Fused prep kernel: blockIdx.y selects task.
// =====================================================================
__global__ void prep_all_kernel(
    const float* __restrict__ x,   float* __restrict__ xr,
    const float* __restrict__ W1f, float* __restrict__ Wt1f,
    const float* __restrict__ W1b, float* __restrict__ Wt1b,
    const float* __restrict__ W2f, float* __restrict__ Wt2f,
    const float* __restrict__ W2b, float* __restrict__ Wt2b,
    const float* __restrict__ Wd,  float* __restrict__ Wtd)
{
    const int task = blockIdx.y;
    if (task == 0) {
        const int n4 = 8388608;
        for (int i = blockIdx.x * 256 + threadIdx.x; i < n4; i += 2048 * 256) {
            float4 v = ((const float4*)x)[i];
            ((float4*)xr)[i] = make_float4(to_tf32(v.x), to_tf32(v.y),
                                           to_tf32(v.z), to_tf32(v.w));
        }
        return;
    }
    const float* W; float* Wt; int K, N;
    switch (task) {
        case 1: W = W1f; Wt = Wt1f; K = 512;  N = 2048; break;
        case 2: W = W1b; Wt = Wt1b; K = 512;  N = 2048; break;
        case 3: W = W2f; Wt = Wt2f; K = 1024; N = 2048; break;
        case 4: W = W2b; Wt = Wt2b; K = 1024; N = 2048; break;
        default: W = Wd; Wt = Wtd; K = 1024; N = 512; break;
    }
    const int nkb = K / 32;
    const int total = nkb * (N / 32);
    const int bx = blockIdx.x;
    if (bx >= total) return;
    __shared__ float tile[32][33];
    const int kb = (bx % nkb) * 32, nb = (bx / nkb) * 32;
    const int tx = threadIdx.x & 31, ty = threadIdx.x >> 5;
#pragma unroll
    for (int i = ty; i < 32; i += 8)
        tile[i][tx] = W[(size_t)(kb + i) * N + nb + tx];
    __syncthreads();
#pragma unroll
    for (int i = ty; i < 32; i += 8)
        Wt[(size_t)(nb + i) * K + kb + tx] = to_tf32(tile[tx][i]);
}

// hsum = tf32(h1 + h2)
__global__ void add_round_kernel(const float* __restrict__ a, const float* __restrict__ b,
                                 float* __restrict__ o, int n4)
{
    int i = blockIdx.x * blockDim.x + threadIdx.x;
    if (i < n4) {
        float4 va = ((const float4*)a)[i];
        float4 vb = ((const float4*)b)[i];
        ((float4*)o)[i] = make_float4(to_tf32(va.x + vb.x), to_tf32(va.y + vb.y),
                                      to_tf32(va.z + vb.z), to_tf32(va.w + vb.w));
    }
}

// =====================================================================
//  TF32 mma.sync GEMM (validated R4):  C = A @ Bt^T (+bias)
//  SCATTER 1: out layout [t][b][N] (row r -> t=r&1023, b=r>>10)
//  SCATTER 0: out row-major
// =====================================================================
#define ABUF 4608   // 128*36 floats per buffer

template <int SCATTER>
__global__ void __launch_bounds__(256, 2)
mma_gemm_kernel(const float* __restrict__ A, const float* __restrict__ Bt,
                const float* __restrict__ bias, float* __restrict__ C, int K, int N)
{
    extern __shared__ float smf[];
    const int tid = threadIdx.x;
    const int wid = tid >> 5, lane = tid & 31;
    const int warp_m = wid & 1, warp_n = wid >> 1;
    const size_t rowBase = (size_t)blockIdx.y * 128;
    const size_t colBase = (size_t)blockIdx.x * 128;
    const uint32_t smbase = smem_u32(smf);
    const int NS = K >> 5;

    float acc[4][4][4];
#pragma unroll
    for (int mi = 0; mi < 4; ++mi)
#pragma unroll
        for (int ni = 0; ni < 4; ++ni)
#pragma unroll
            for (int r = 0; r < 4; ++r) acc[mi][ni][r] = 0.f;

    auto cp_tile = [&](int s, int p) {
        const int kt = s << 5;
#pragma unroll
        for (int i = 0; i < 4; ++i) {
            int idx = i * 256 + tid;
            int row = idx >> 3, f4 = idx & 7;
            uint32_t da = smbase + (uint32_t)((p * ABUF + row * 36 + f4 * 4) << 2);
            cp16(da, A + (rowBase + row) * K + kt + f4 * 4);
            uint32_t db = smbase + (uint32_t)(((2 * ABUF) + p * ABUF + row * 36 + f4 * 4) << 2);
            cp16(db, Bt + (colBase + row) * K + kt + f4 * 4);
        }
        asm volatile("cp.async.commit_group;");
    };

    cp_tile(0, 0);
    cp_tile(1, 1);

    const int g = lane >> 2, c = lane & 3;
    const int ar0 = warp_m * 64 + g;
    const int bn0 = warp_n * 32 + g;

    for (int s = 0; s < NS; ++s) {
        const int p = s & 1;
        if (s + 1 < NS) asm volatile("cp.async.wait_group 1;");
        else            asm volatile("cp.async.wait_group 0;");
        __syncthreads();

        const float* Ab = smf + p * ABUF;
        const float* Bb = smf + 2 * ABUF + p * ABUF;

#pragma unroll
        for (int k8 = 0; k8 < 4; ++k8) {
            const int kc = k8 * 8 + c;
            uint32_t a[4][4], b[4][2];
#pragma unroll
            for (int mi = 0; mi < 4; ++mi) {
                const float* base = Ab + (ar0 + mi * 16) * 36 + kc;
                a[mi][0] = __float_as_uint(base[0]);
                a[mi][1] = __float_as_uint(base[8 * 36]);
                a[mi][2] = __float_as_uint(base[4]);
                a[mi][3] = __float_as_uint(base[8 * 36 + 4]);
            }
#pragma unroll
            for (int ni = 0; ni < 4; ++ni) {
                const float* base = Bb + (bn0 + ni * 8) * 36 + kc;
                b[ni][0] = __float_as_uint(base[0]);
                b[ni][1] = __float_as_uint(base[4]);
            }
#pragma unroll
            for (int mi = 0; mi < 4; ++mi)
#pragma unroll
                for (int ni = 0; ni < 4; ++ni)
                    asm volatile(
                        "mma.sync.aligned.m16n8k8.row.col.f32.tf32.tf32.f32 "
                        "{%0,%1,%2,%3}, {%4,%5,%6,%7}, {%8,%9}, {%0,%1,%2,%3};"
                        : "+f"(acc[mi][ni][0]), "+f"(acc[mi][ni][1]),
                          "+f"(acc[mi][ni][2]), "+f"(acc[mi][ni][3])
                        : "r"(a[mi][0]), "r"(a[mi][1]), "r"(a[mi][2]), "r"(a[mi][3]),
                          "r"(b[ni][0]), "r"(b[ni][1]));
        }
        __syncthreads();
        if (s + 2 < NS) cp_tile(s + 2, p);
    }

    const int c2 = (lane & 3) * 2;
#pragma unroll
    for (int mi = 0; mi < 4; ++mi) {
        size_t r0 = rowBase + warp_m * 64 + mi * 16 + g;
        size_t r8 = r0 + 8;
        size_t off0, off8;
        if (SCATTER) {
            off0 = (((r0 & 1023) << 6) + (r0 >> 10)) * (size_t)N;
            off8 = (((r8 & 1023) << 6) + (r8 >> 10)) * (size_t)N;
        } else {
            off0 = r0 * (size_t)N;
            off8 = r8 * (size_t)N;
        }
#pragma unroll
        for (int ni = 0; ni < 4; ++ni) {
            size_t col = colBase + warp_n * 32 + ni * 8 + c2;
            float2 bv = *(const float2*)&bias[col];
            float2 v0 = make_float2(acc[mi][ni][0] + bv.x, acc[mi][ni][1] + bv.y);
            float2 v1 = make_float2(acc[mi][ni][2] + bv.x, acc[mi][ni][3] + bv.y);
            *(float2*)&C[off0 + col] = v0;
            *(float2*)&C[off8 + col] = v1;
        }
    }
}

// =====================================================================
//  Persistent bidirectional LSTM layer — tensor-core recurrence.
//  EXACT R12 version (17.09 ms measured).
// =====================================================================
__device__ __forceinline__ void bar_arrive(int dir)
{
    __threadfence();
    __syncthreads();
    if (threadIdx.x == 0) atomicAdd(&g_bar2[dir * 32], 1u);
}
__device__ __forceinline__ void bar_wait(int dir, unsigned int target)
{
    if (threadIdx.x == 0)
        while (*(volatile unsigned int*)&g_bar2[dir * 32] < target) { }
    __syncthreads();
}

#define LSTM_SMEM ((36864 + 4 * 32 * 66) * 4)

template <int ROUND>
__global__ void __launch_bounds__(256, 1)
lstm_mma_kernel(const float* __restrict__ Zf, const float* __restrict__ Zb,
                const float* __restrict__ Uf, const float* __restrict__ Ub,
                float* __restrict__ hout)
{
    extern __shared__ float sm[];
    float* hs   = sm;           // [4 ks][128 k][72]  (pad-72)
    float* zred = sm + 36864;   // [4 ks][32 l][66]

    const int tid = threadIdx.x;
    const int w = tid >> 5, lane = tid & 31;
    const int g = lane >> 2, c = lane & 3;
    const int ks = w >> 1, mg = w & 1;
    const int dir = blockIdx.x >> 6;
    const int jb  = blockIdx.x & 63;
    const float* U = dir ? Ub : Uf;
    const float* Z = dir ? Zb : Zf;
    float* hst0 = &g_hst[dir][0][0][0];
    float* hst1 = &g_hst[dir][1][0][0];

    // ---- one-time: U A-fragments (tf32-rounded), registers ----
    float uhi[16][4];
    {
        const int l0 = mg * 16 + g, l1 = l0 + 8;
        const int gc0 = (l0 >> 3) * 512 + jb * 8 + (l0 & 7);
        const int gc1 = (l1 >> 3) * 512 + jb * 8 + (l1 & 7);
#pragma unroll
        for (int kk = 0; kk < 16; ++kk) {
            int k = ks * 128 + kk * 8;
            uhi[kk][0] = to_tf32(U[(size_t)(k + c) * 2048 + gc0]);
            uhi[kk][1] = to_tf32(U[(size_t)(k + c) * 2048 + gc1]);
            uhi[kk][2] = to_tf32(U[(size_t)(k + c + 4) * 2048 + gc0]);
            uhi[kk][3] = to_tf32(U[(size_t)(k + c + 4) * 2048 + gc1]);
        }
    }

    // zero own cols of phase-0 state
    for (int i = tid; i < 512; i += 256) hst0[jb * 8 * 64 + i] = 0.f;
    bar_arrive(dir);
    bar_wait(dir, 64u);

    const int eb = tid >> 2;
    const int q0 = (tid & 3) * 2;
    float cst0 = 0.f, cst1 = 0.f;
    const int pt = tid & 63;
    float* hsP = hs + ks * 9216;
    const uint32_t hsPb = smem_u32(hsP);

    // prologue Z prefetch for s=0
    float2 zi2, zf2, zg2, zo2;
    {
        int t0 = dir ? (TSTEPS - 1) : 0;
        const float* Zt = Z + ((size_t)t0 * 64 + eb) * 2048 + jb * 8 + q0;
        zi2 = *(const float2*)(Zt + 0);
        zf2 = *(const float2*)(Zt + 512);
        zg2 = *(const float2*)(Zt + 1024);
        zo2 = *(const float2*)(Zt + 1536);
    }

    for (int s = 0; s < TSTEPS; ++s) {
        const int t = dir ? (TSTEPS - 1 - s) : s;
        const float* hsrc = (s & 1) ? hst1 : hst0;
        float* hdst = (s & 1) ? hst0 : hst1;

        // ---- stage pair's K-slice via cp.async: [col][b] -> smem [k][72] ----
        {
            const float4* src = (const float4*)(hsrc + ks * 8192);
#pragma unroll
            for (int i = 0; i < 32; ++i) {
                int idx = i * 64 + pt;
                int kl = idx >> 4, q4 = idx & 15;
                cp16(hsPb + (uint32_t)((kl * 72 + q4 * 4) << 2), src + idx);
            }
            asm volatile("cp.async.commit_group;");
            asm volatile("cp.async.wait_group 0;");
        }
        asm volatile("bar.sync %0, %1;" :: "r"(1 + ks), "r"(64) : "memory");

        // ---- MMA: z[l=mg*16..+16][b=0..63] over k in [ks*128,+128) ----
        float acc[8][4];
#pragma unroll
        for (int nt = 0; nt < 8; ++nt)
#pragma unroll
            for (int r = 0; r < 4; ++r) acc[nt][r] = 0.f;

#pragma unroll
        for (int kk = 0; kk < 16; ++kk) {
            uint32_t ah0 = __float_as_uint(uhi[kk][0]), ah1 = __float_as_uint(uhi[kk][1]);
            uint32_t ah2 = __float_as_uint(uhi[kk][2]), ah3 = __float_as_uint(uhi[kk][3]);
            const uint32_t* rowA = (const uint32_t*)(hsP + (kk * 8 + c) * 72);
            const uint32_t* rowB = rowA + 4 * 72;
#pragma unroll
            for (int nt = 0; nt < 8; ++nt) {
                uint32_t b0 = rowA[nt * 8 + g];
                uint32_t b1 = rowB[nt * 8 + g];
                asm volatile(
                    "mma.sync.aligned.m16n8k8.row.col.f32.tf32.tf32.f32 "
                    "{%0,%1,%2,%3}, {%4,%5,%6,%7}, {%8,%9}, {%0,%1,%2,%3};"
                    : "+f"(acc[nt][0]), "+f"(acc[nt][1]), "+f"(acc[nt][2]), "+f"(acc[nt][3])
                    : "r"(ah0), "r"(ah1), "r"(ah2), "r"(ah3),
                      "r"(b0), "r"(b1));
            }
        }

        // ---- store partials: zred[ks][l][b] ----
#pragma unroll
        for (int nt = 0; nt < 8; ++nt) {
            int l0 = mg * 16 + g;
            int n0 = nt * 8 + c * 2;
            *(float2*)&zred[(ks * 32 + l0) * 66 + n0]     = make_float2(acc[nt][0], acc[nt][1]);
            *(float2*)&zred[(ks * 32 + l0 + 8) * 66 + n0] = make_float2(acc[nt][2], acc[nt][3]);
        }
        __syncthreads();

        // ---- gate epilogue ----
        float hh0, hh1;
        {
            float vi0 = zi2.x, vi1 = zi2.y, vf0 = zf2.x, vf1 = zf2.y;
            float vg0 = zg2.x, vg1 = zg2.y, vo0 = zo2.x, vo1 = zo2.y;
#pragma unroll
            for (int k = 0; k < 4; ++k) {
                vi0 += zred[(k * 32 + q0)      * 66 + eb];
                vi1 += zred[(k * 32 + q0 + 1)  * 66 + eb];
                vf0 += zred[(k * 32 + 8 + q0)  * 66 + eb];
                vf1 += zred[(k * 32 + 9 + q0)  * 66 + eb];
                vg0 += zred[(k * 32 + 16 + q0) * 66 + eb];
                vg1 += zred[(k * 32 + 17 + q0) * 66 + eb];
                vo0 += zred[(k * 32 + 24 + q0) * 66 + eb];
                vo1 += zred[(k * 32 + 25 + q0) * 66 + eb];
            }
            float ig0 = fsigm(vi0), ig1 = fsigm(vi1);
            float fg0 = fsigm(vf0), fg1 = fsigm(vf1);
            float gg0 = ftanh(vg0), gg1 = ftanh(vg1);
            float og0 = fsigm(vo0), og1 = fsigm(vo1);
            cst0 = fg0 * cst0 + ig0 * gg0;
            cst1 = fg1 * cst1 + ig1 * gg1;
            hh0 = og0 * ftanh(cst0);
            hh1 = og1 * ftanh(cst1);

            __stcg(&hdst[(jb * 8 + q0) * 64 + eb],     to_tf32(hh0));
            __stcg(&hdst[(jb * 8 + q0 + 1) * 64 + eb], to_tf32(hh1));
        }

        bar_arrive(dir);

        size_t ho = ((size_t)eb * 1024 + t) * 1024 + dir * 512 + jb * 8 + q0;
        if (ROUND) {
            hout[ho]     = to_tf32(hh0);
            hout[ho + 1] = to_tf32(hh1);
        } else {
            hout[ho]     = hh0;
            hout[ho + 1] = hh1;
        }

        if (s + 1 < TSTEPS) {
            int tn = dir ? (TSTEPS - 2 - s) : (s + 1);
            const float* Zt = Z + ((size_t)tn * 64 + eb) * 2048 + jb * 8 + q0;
            zi2 = *(const float2*)(Zt + 0);
            zf2 = *(const float2*)(Zt + 512);
            zg2 = *(const float2*)(Zt + 1024);
            zo2 = *(const float2*)(Zt + 1536);
            bar_wait(dir, 64u * (unsigned)(s + 2));
        }
    }
}

__global__ void reset_bar_kernel() { g_bar2[0] = 0u; g_bar2[32] = 0u; }

// =====================================================================
extern "C" void kernel_launch(void* const* d_in, const int* in_sizes, int n_in,
                              void* d_out, int out_size)
{
    (void)in_sizes; (void)n_in; (void)out_size;
    const float* x   = (const float*)d_in[0];
    const float* W1f = (const float*)d_in[1];
    const float* U1f = (const float*)d_in[2];
    const float* b1f = (const float*)d_in[3];
    const float* W1b = (const float*)d_in[4];
    const float* U1b = (const float*)d_in[5];
    const float* b1b = (const float*)d_in[6];
    const float* W2f = (const float*)d_in[7];
    const float* U2f = (const float*)d_in[8];
    const float* b2f = (const float*)d_in[9];
    const float* W2b = (const float*)d_in[10];
    const float* U2b = (const float*)d_in[11];
    const float* b2b = (const float*)d_in[12];
    const float* Wd  = (const float*)d_in[13];
    const float* bd  = (const float*)d_in[14];
    float* out = (float*)d_out;

    float *Zf, *Zb, *h1, *h2, *xr;
    float *Wt1f, *Wt1b, *Wt2f, *Wt2b, *Wtd;
    cudaGetSymbolAddress((void**)&Zf, g_Zf);
    cudaGetSymbolAddress((void**)&Zb, g_Zb);
    cudaGetSymbolAddress((void**)&h1, g_h1);
    cudaGetSymbolAddress((void**)&h2, g_h2);
    cudaGetSymbolAddress((void**)&xr, g_xr);
    cudaGetSymbolAddress((void**)&Wt1f, g_Wt1f);
    cudaGetSymbolAddress((void**)&Wt1b, g_Wt1b);
    cudaGetSymbolAddress((void**)&Wt2f, g_Wt2f);
    cudaGetSymbolAddress((void**)&Wt2b, g_Wt2b);
    cudaGetSymbolAddress((void**)&Wtd, g_Wtd);

    const int GEMM_SMEM = 4 * ABUF * 4;
    cudaFuncSetAttribute(mma_gemm_kernel<0>, cudaFuncAttributeMaxDynamicSharedMemorySize, GEMM_SMEM);
    cudaFuncSetAttribute(mma_gemm_kernel<1>, cudaFuncAttributeMaxDynamicSharedMemorySize, GEMM_SMEM);
    cudaFuncSetAttribute(lstm_mma_kernel<0>, cudaFuncAttributeMaxDynamicSharedMemorySize, LSTM_SMEM);
    cudaFuncSetAttribute(lstm_mma_kernel<1>, cudaFuncAttributeMaxDynamicSharedMemorySize, LSTM_SMEM);

    dim3 blk(256);
    dim3 gZ(2048 / 128, 65536 / 128);
    dim3 gO(512 / 128, 65536 / 128);

    prep_all_kernel<<<dim3(2048, 6), 256>>>(x, xr, W1f, Wt1f, W1b, Wt1b,
                                            W2f, Wt2f, W2b, Wt2b, Wd, Wtd);
    // Z projections MUST use SCATTER=1 ([t][b][4H] layout read by the LSTM)
    mma_gemm_kernel<1><<<gZ, blk, GEMM_SMEM>>>(xr, Wt1f, b1f, Zf, 512, 2048);
    mma_gemm_kernel<1><<<gZ, blk, GEMM_SMEM>>>(xr, Wt1b, b1b, Zb, 512, 2048);
    reset_bar_kernel<<<1, 1>>>();

    // layer-1 recurrence
    lstm_mma_kernel<1><<<128, 256, LSTM_SMEM>>>(Zf, Zb, U1f, U1b, h1);

    // layer-2 input projections (SCATTER=1)
    mma_gemm_kernel<1><<<gZ, blk, GEMM_SMEM>>>(h1, Wt2f, b2f, Zf, 1024, 2048);
    mma_gemm_kernel<1><<<gZ, blk, GEMM_SMEM>>>(h1, Wt2b, b2b, Zb, 1024, 2048);

    // layer-2 recurrence
    reset_bar_kernel<<<1, 1>>>();
    lstm_mma_kernel<0><<<128, 256, LSTM_SMEM>>>(Zf, Zb, U2f, U2b, h2);

    // dense head (single tf32 GEMM, row-major out): out = tf32(h1+h2) @ Wtd + bd
    add_round_kernel<<<(16777216 + 255) / 256, 256>>>(h1, h2, Zf, 16777216);
    mma_gemm_kernel<0><<<gO, blk, GEMM_SMEM>>>(Zf, Wtd, bd, out, 1024, 512);
}

// round 16
// speedup vs baseline: 1.3966x; 1.1035x over previous
#include <cuda_runtime.h>
#include <cuda_bf16.h>
#include <math.h>
#include <stdint.h>

#define TSTEPS 1024
#define BATCH  64
#define HID    512

// ---------------- scratch (static device allocations; no cudaMalloc) ----------------
__device__ float g_Zf[(size_t)TSTEPS * BATCH * 2048];   // Z fwd [t][b][4H]; later hsum
__device__ float g_Zb[(size_t)TSTEPS * BATCH * 2048];   // Z bwd [t][b][4H]
__device__ float g_h1[(size_t)BATCH * TSTEPS * 1024];   // layer1 out [b][t][2H] (tf32)
__device__ float g_h2[(size_t)BATCH * TSTEPS * 1024];   // layer2 out [b][t][2H] (fp32)
__device__ float g_xr[(size_t)BATCH * TSTEPS * 512];    // tf32-rounded x
// h state, bf16x2 packed: [dir][phase][kword(=col/2)][b]  (word = (h[2kw], h[2kw+1]))
__device__ uint32_t g_hstB[2][2][256 * 64];
__device__ unsigned int g_bar2[64];                     // per-dir barrier counters ([0],[32])

// transposed + tf32-rounded weights [N][K]
__device__ float g_Wt1f[2048 * 512];
__device__ float g_Wt1b[2048 * 512];
__device__ float g_Wt2f[2048 * 1024];
__device__ float g_Wt2b[2048 * 1024];
__device__ float g_Wtd [512 * 1024];

__device__ __forceinline__ float to_tf32(float v) {
    float r; asm("cvt.rna.tf32.f32 %0, %1;" : "=f"(r) : "f"(v)); return r;
}
__device__ __forceinline__ uint32_t smem_u32(const void* p) {
    uint32_t a;
    asm("{ .reg .u64 t; cvta.to.shared.u64 t, %1; cvt.u32.u64 %0, t; }" : "=r"(a) : "l"(p));
    return a;
}
__device__ __forceinline__ float fsigm(float x) { return 1.f / (1.f + __expf(-x)); }
__device__ __forceinline__ float ftanh(float x) {
    float e = __expf(2.f * x);
    return 1.f - __fdividef(2.f, e + 1.f);
}
__device__ __forceinline__ void cp16(uint32_t dst, const void* src) {
    asm volatile("cp.async.cg.shared.global [%0], [%1], 16;" :: "r"(dst), "l"(src));
}
__device__ __forceinline__ uint32_t pack_bf2(float a, float b) {
    __nv_bfloat16 ha = __float2bfloat16(a), hb = __float2bfloat16(b);
    return (uint32_t)__bfloat16_as_ushort(ha) | ((uint32_t)__bfloat16_as_ushort(hb) << 16);
}

// =====================================================================
//  Fused prep kernel: blockIdx.y selects task.
// =====================================================================
__global__ void prep_all_kernel(
    const float* __restrict__ x,   float* __restrict__ xr,
    const float* __restrict__ W1f, float* __restrict__ Wt1f,
    const float* __restrict__ W1b, float* __restrict__ Wt1b,
    const float* __restrict__ W2f, float* __restrict__ Wt2f,
    const float* __restrict__ W2b, float* __restrict__ Wt2b,
    const float* __restrict__ Wd,  float* __restrict__ Wtd)
{
    const int task = blockIdx.y;
    if (task == 0) {
        const int n4 = 8388608;
        for (int i = blockIdx.x * 256 + threadIdx.x; i < n4; i += 2048 * 256) {
            float4 v = ((const float4*)x)[i];
            ((float4*)xr)[i] = make_float4(to_tf32(v.x), to_tf32(v.y),
                                           to_tf32(v.z), to_tf32(v.w));
        }
        return;
    }
    const float* W; float* Wt; int K, N;
    switch (task) {
        case 1: W = W1f; Wt = Wt1f; K = 512;  N = 2048; break;
        case 2: W = W1b; Wt = Wt1b; K = 512;  N = 2048; break;
        case 3: W = W2f; Wt = Wt2f; K = 1024; N = 2048; break;
        case 4: W = W2b; Wt = Wt2b; K = 1024; N = 2048; break;
        default: W = Wd; Wt = Wtd; K = 1024; N = 512; break;
    }
    const int nkb = K / 32;
    const int total = nkb * (N / 32);
    const int bx = blockIdx.x;
    if (bx >= total) return;
    __shared__ float tile[32][33];
    const int kb = (bx % nkb) * 32, nb = (bx / nkb) * 32;
    const int tx = threadIdx.x & 31, ty = threadIdx.x >> 5;
#pragma unroll
    for (int i = ty; i < 32; i += 8)
        tile[i][tx] = W[(size_t)(kb + i) * N + nb + tx];
    __syncthreads();
#pragma unroll
    for (int i = ty; i < 32; i += 8)
        Wt[(size_t)(nb + i) * K + kb + tx] = to_tf32(tile[tx][i]);
}

// hsum = tf32(h1 + h2)
__global__ void add_round_kernel(const float* __restrict__ a, const float* __restrict__ b,
                                 float* __restrict__ o, int n4)
{
    int i = blockIdx.x * blockDim.x + threadIdx.x;
    if (i < n4) {
        float4 va = ((const float4*)a)[i];
        float4 vb = ((const float4*)b)[i];
        ((float4*)o)[i] = make_float4(to_tf32(va.x + vb.x), to_tf32(va.y + vb.y),
                                      to_tf32(va.z + vb.z), to_tf32(va.w + vb.w));
    }
}

// =====================================================================
//  TF32 mma.sync GEMM (validated R4):  C = A @ Bt^T (+bias)
//  SCATTER 1: out layout [t][b][N]   SCATTER 0: row-major
// =====================================================================
#define ABUF 4608   // 128*36 floats per buffer

template <int SCATTER>
__global__ void __launch_bounds__(256, 2)
mma_gemm_kernel(const float* __restrict__ A, const float* __restrict__ Bt,
                const float* __restrict__ bias, float* __restrict__ C, int K, int N)
{
    extern __shared__ float smf[];
    const int tid = threadIdx.x;
    const int wid = tid >> 5, lane = tid & 31;
    const int warp_m = wid & 1, warp_n = wid >> 1;
    const size_t rowBase = (size_t)blockIdx.y * 128;
    const size_t colBase = (size_t)blockIdx.x * 128;
    const uint32_t smbase = smem_u32(smf);
    const int NS = K >> 5;

    float acc[4][4][4];
#pragma unroll
    for (int mi = 0; mi < 4; ++mi)
#pragma unroll
        for (int ni = 0; ni < 4; ++ni)
#pragma unroll
            for (int r = 0; r < 4; ++r) acc[mi][ni][r] = 0.f;

    auto cp_tile = [&](int s, int p) {
        const int kt = s << 5;
#pragma unroll
        for (int i = 0; i < 4; ++i) {
            int idx = i * 256 + tid;
            int row = idx >> 3, f4 = idx & 7;
            uint32_t da = smbase + (uint32_t)((p * ABUF + row * 36 + f4 * 4) << 2);
            cp16(da, A + (rowBase + row) * K + kt + f4 * 4);
            uint32_t db = smbase + (uint32_t)(((2 * ABUF) + p * ABUF + row * 36 + f4 * 4) << 2);
            cp16(db, Bt + (colBase + row) * K + kt + f4 * 4);
        }
        asm volatile("cp.async.commit_group;");
    };

    cp_tile(0, 0);
    cp_tile(1, 1);

    const int g = lane >> 2, c = lane & 3;
    const int ar0 = warp_m * 64 + g;
    const int bn0 = warp_n * 32 + g;

    for (int s = 0; s < NS; ++s) {
        const int p = s & 1;
        if (s + 1 < NS) asm volatile("cp.async.wait_group 1;");
        else            asm volatile("cp.async.wait_group 0;");
        __syncthreads();

        const float* Ab = smf + p * ABUF;
        const float* Bb = smf + 2 * ABUF + p * ABUF;

#pragma unroll
        for (int k8 = 0; k8 < 4; ++k8) {
            const int kc = k8 * 8 + c;
            uint32_t a[4][4], b[4][2];
#pragma unroll
            for (int mi = 0; mi < 4; ++mi) {
                const float* base = Ab + (ar0 + mi * 16) * 36 + kc;
                a[mi][0] = __float_as_uint(base[0]);
                a[mi][1] = __float_as_uint(base[8 * 36]);
                a[mi][2] = __float_as_uint(base[4]);
                a[mi][3] = __float_as_uint(base[8 * 36 + 4]);
            }
#pragma unroll
            for (int ni = 0; ni < 4; ++ni) {
                const float* base = Bb + (bn0 + ni * 8) * 36 + kc;
                b[ni][0] = __float_as_uint(base[0]);
                b[ni][1] = __float_as_uint(base[4]);
            }
#pragma unroll
            for (int mi = 0; mi < 4; ++mi)
#pragma unroll
                for (int ni = 0; ni < 4; ++ni)
                    asm volatile(
                        "mma.sync.aligned.m16n8k8.row.col.f32.tf32.tf32.f32 "
                        "{%0,%1,%2,%3}, {%4,%5,%6,%7}, {%8,%9}, {%0,%1,%2,%3};"
                        : "+f"(acc[mi][ni][0]), "+f"(acc[mi][ni][1]),
                          "+f"(acc[mi][ni][2]), "+f"(acc[mi][ni][3])
                        : "r"(a[mi][0]), "r"(a[mi][1]), "r"(a[mi][2]), "r"(a[mi][3]),
                          "r"(b[ni][0]), "r"(b[ni][1]));
        }
        __syncthreads();
        if (s + 2 < NS) cp_tile(s + 2, p);
    }

    const int c2 = (lane & 3) * 2;
#pragma unroll
    for (int mi = 0; mi < 4; ++mi) {
        size_t r0 = rowBase + warp_m * 64 + mi * 16 + g;
        size_t r8 = r0 + 8;
        size_t off0, off8;
        if (SCATTER) {
            off0 = (((r0 & 1023) << 6) + (r0 >> 10)) * (size_t)N;
            off8 = (((r8 & 1023) << 6) + (r8 >> 10)) * (size_t)N;
        } else {
            off0 = r0 * (size_t)N;
            off8 = r8 * (size_t)N;
        }
#pragma unroll
        for (int ni = 0; ni < 4; ++ni) {
            size_t col = colBase + warp_n * 32 + ni * 8 + c2;
            float2 bv = *(const float2*)&bias[col];
            float2 v0 = make_float2(acc[mi][ni][0] + bv.x, acc[mi][ni][1] + bv.y);
            float2 v1 = make_float2(acc[mi][ni][2] + bv.x, acc[mi][ni][3] + bv.y);
            *(float2*)&C[off0 + col] = v0;
            *(float2*)&C[off8 + col] = v1;
        }
    }
}

// =====================================================================
//  Persistent bidirectional LSTM layer — bf16 tensor-core recurrence.
//  R16: h state transported as packed bf16x2 ([kword][b]) — halves the
//  16 MB/step L2 staging (the LTS-bound term). MMA = m16n8k16 bf16 with
//  U split into bf16 hi+lo A-fragments (U precision ~2^-16, only h
//  carries bf16 noise). Same 128 MMAs/warp/step; half the LDS; smem 105KB.
// =====================================================================
__device__ __forceinline__ void bar_arrive(int dir)
{
    __threadfence();
    __syncthreads();
    if (threadIdx.x == 0) atomicAdd(&g_bar2[dir * 32], 1u);
}
__device__ __forceinline__ void bar_wait(int dir, unsigned int target)
{
    if (threadIdx.x == 0)
        while (*(volatile unsigned int*)&g_bar2[dir * 32] < target) { }
    __syncthreads();
}

#define LSTM_SMEM ((4 * 64 * 72 + 4 * 32 * 66) * 4)   // 107,520 B

template <int ROUND>
__global__ void __launch_bounds__(256, 1)
lstm_mma_kernel(const float* __restrict__ Zf, const float* __restrict__ Zb,
                const float* __restrict__ Uf, const float* __restrict__ Ub,
                float* __restrict__ hout)
{
    extern __shared__ float sm[];
    uint32_t* hsw = (uint32_t*)sm;      // [4 ks][64 kw][72] bf16x2 words
    float* zred = sm + 18432;           // [4 ks][32 l][66]

    const int tid = threadIdx.x;
    const int w = tid >> 5, lane = tid & 31;
    const int g = lane >> 2, c = lane & 3;
    const int ks = w >> 1, mg = w & 1;
    const int dir = blockIdx.x >> 6;
    const int jb  = blockIdx.x & 63;
    const float* U = dir ? Ub : Uf;
    const float* Z = dir ? Zb : Zf;
    uint32_t* hstB0 = &g_hstB[dir][0][0];
    uint32_t* hstB1 = &g_hstB[dir][1][0];

    // ---- one-time: U A-fragments (bf16 hi+lo split), registers ----
    // m16n8k16 A map: a0=(l0, k0..k0+1) a1=(l1, same) a2=(l0, k0+8..+9) a3=(l1, same)
    uint32_t uhi[8][4], ulo[8][4];
    {
        const int l0 = mg * 16 + g, l1 = l0 + 8;
        const int gc0 = (l0 >> 3) * 512 + jb * 8 + (l0 & 7);
        const int gc1 = (l1 >> 3) * 512 + jb * 8 + (l1 & 7);
#pragma unroll
        for (int kk = 0; kk < 8; ++kk) {
            int kb = ks * 128 + kk * 16;
#pragma unroll
            for (int r = 0; r < 4; ++r) {
                int k0 = kb + 2 * c + ((r >> 1) ? 8 : 0);
                int gc = (r & 1) ? gc1 : gc0;
                float v0 = U[(size_t)k0 * 2048 + gc];
                float v1 = U[(size_t)(k0 + 1) * 2048 + gc];
                __nv_bfloat16 h0 = __float2bfloat16(v0);
                __nv_bfloat16 h1 = __float2bfloat16(v1);
                uhi[kk][r] = (uint32_t)__bfloat16_as_ushort(h0) |
                             ((uint32_t)__bfloat16_as_ushort(h1) << 16);
                ulo[kk][r] = pack_bf2(v0 - __bfloat162float(h0),
                                      v1 - __bfloat162float(h1));
            }
        }
    }

    // zero own kwords of phase-0 state (kw jb*4..+4, all b = 256 words)
    hstB0[jb * 256 + tid] = 0u;
    bar_arrive(dir);
    bar_wait(dir, 64u);

    const int eb = tid >> 2;
    const int q0 = (tid & 3) * 2;
    float cst0 = 0.f, cst1 = 0.f;
    const int pt = tid & 63;
    uint32_t* hsP = hsw + ks * 4608;
    const uint32_t hsPb = smem_u32(hsP);

    // prologue Z prefetch for s=0
    float2 zi2, zf2, zg2, zo2;
    {
        int t0 = dir ? (TSTEPS - 1) : 0;
        const float* Zt = Z + ((size_t)t0 * 64 + eb) * 2048 + jb * 8 + q0;
        zi2 = *(const float2*)(Zt + 0);
        zf2 = *(const float2*)(Zt + 512);
        zg2 = *(const float2*)(Zt + 1024);
        zo2 = *(const float2*)(Zt + 1536);
    }

    for (int s = 0; s < TSTEPS; ++s) {
        const int t = dir ? (TSTEPS - 1 - s) : s;
        const uint32_t* hsrc = (s & 1) ? hstB1 : hstB0;
        uint32_t* hdst = (s & 1) ? hstB0 : hstB1;

        // ---- stage pair's K-slice via cp.async: [kw][b] words, 16 KB/pair ----
        {
            const float4* src = (const float4*)(hsrc + ks * 4096);
#pragma unroll
            for (int i = 0; i < 16; ++i) {
                int idx = i * 64 + pt;          // float4 index 0..1023
                int kl = idx >> 4, q4 = idx & 15;
                cp16(hsPb + (uint32_t)((kl * 72 + q4 * 4) << 2), src + idx);
            }
            asm volatile("cp.async.commit_group;");
            asm volatile("cp.async.wait_group 0;");
        }
        asm volatile("bar.sync %0, %1;" :: "r"(1 + ks), "r"(64) : "memory");

        // ---- bf16 MMA: z[l][b] over k in [ks*128,+128), 8 k16-chunks ----
        float acc[8][4];
#pragma unroll
        for (int nt = 0; nt < 8; ++nt)
#pragma unroll
            for (int r = 0; r < 4; ++r) acc[nt][r] = 0.f;

#pragma unroll
        for (int kk = 0; kk < 8; ++kk) {
            uint32_t ah0 = uhi[kk][0], ah1 = uhi[kk][1], ah2 = uhi[kk][2], ah3 = uhi[kk][3];
            uint32_t al0 = ulo[kk][0], al1 = ulo[kk][1], al2 = ulo[kk][2], al3 = ulo[kk][3];
            const uint32_t* rowA = hsP + (kk * 8 + c) * 72;
            const uint32_t* rowB = rowA + 4 * 72;
#pragma unroll
            for (int nt = 0; nt < 8; ++nt) {
                uint32_t b0 = rowA[nt * 8 + g];
                uint32_t b1 = rowB[nt * 8 + g];
                asm volatile(
                    "mma.sync.aligned.m16n8k16.row.col.f32.bf16.bf16.f32 "
                    "{%0,%1,%2,%3}, {%4,%5,%6,%7}, {%8,%9}, {%0,%1,%2,%3};"
                    : "+f"(acc[nt][0]), "+f"(acc[nt][1]), "+f"(acc[nt][2]), "+f"(acc[nt][3])
                    : "r"(ah0), "r"(ah1), "r"(ah2), "r"(ah3),
                      "r"(b0), "r"(b1));
                asm volatile(
                    "mma.sync.aligned.m16n8k16.row.col.f32.bf16.bf16.f32 "
                    "{%0,%1,%2,%3}, {%4,%5,%6,%7}, {%8,%9}, {%0,%1,%2,%3};"
                    : "+f"(acc[nt][0]), "+f"(acc[nt][1]), "+f"(acc[nt][2]), "+f"(acc[nt][3])
                    : "r"(al0), "r"(al1), "r"(al2), "r"(al3),
                      "r"(b0), "r"(b1));
            }
        }

        // ---- store partials: zred[ks][l][b] ----
#pragma unroll
        for (int nt = 0; nt < 8; ++nt) {
            int l0 = mg * 16 + g;
            int n0 = nt * 8 + c * 2;
            *(float2*)&zred[(ks * 32 + l0) * 66 + n0]     = make_float2(acc[nt][0], acc[nt][1]);
            *(float2*)&zred[(ks * 32 + l0 + 8) * 66 + n0] = make_float2(acc[nt][2], acc[nt][3]);
        }
        __syncthreads();

        // ---- gate epilogue ----
        float hh0, hh1;
        {
            float vi0 = zi2.x, vi1 = zi2.y, vf0 = zf2.x, vf1 = zf2.y;
            float vg0 = zg2.x, vg1 = zg2.y, vo0 = zo2.x, vo1 = zo2.y;
#pragma unroll
            for (int k = 0; k < 4; ++k) {
                vi0 += zred[(k * 32 + q0)      * 66 + eb];
                vi1 += zred[(k * 32 + q0 + 1)  * 66 + eb];
                vf0 += zred[(k * 32 + 8 + q0)  * 66 + eb];
                vf1 += zred[(k * 32 + 9 + q0)  * 66 + eb];
                vg0 += zred[(k * 32 + 16 + q0) * 66 + eb];
                vg1 += zred[(k * 32 + 17 + q0) * 66 + eb];
                vo0 += zred[(k * 32 + 24 + q0) * 66 + eb];
                vo1 += zred[(k * 32 + 25 + q0) * 66 + eb];
            }
            float ig0 = fsigm(vi0), ig1 = fsigm(vi1);
            float fg0 = fsigm(vf0), fg1 = fsigm(vf1);
            float gg0 = ftanh(vg0), gg1 = ftanh(vg1);
            float og0 = fsigm(vo0), og1 = fsigm(vo1);
            cst0 = fg0 * cst0 + ig0 * gg0;
            cst1 = fg1 * cst1 + ig1 * gg1;
            hh0 = og0 * ftanh(cst0);
            hh1 = og1 * ftanh(cst1);

            // packed bf16x2 state store: kw = jb*4 + q0/2, one word per thread
            __stcg(&hdst[(jb * 4 + (q0 >> 1)) * 64 + eb], pack_bf2(hh0, hh1));
        }

        bar_arrive(dir);

        size_t ho = ((size_t)eb * 1024 + t) * 1024 + dir * 512 + jb * 8 + q0;
        if (ROUND) {
            hout[ho]     = to_tf32(hh0);
            hout[ho + 1] = to_tf32(hh1);
        } else {
            hout[ho]     = hh0;
            hout[ho + 1] = hh1;
        }

        if (s + 1 < TSTEPS) {
            int tn = dir ? (TSTEPS - 2 - s) : (s + 1);
            const float* Zt = Z + ((size_t)tn * 64 + eb) * 2048 + jb * 8 + q0;
            zi2 = *(const float2*)(Zt + 0);
            zf2 = *(const float2*)(Zt + 512);
            zg2 = *(const float2*)(Zt + 1024);
            zo2 = *(const float2*)(Zt + 1536);
            bar_wait(dir, 64u * (unsigned)(s + 2));
        }
    }
}

__global__ void reset_bar_kernel() { g_bar2[0] = 0u; g_bar2[32] = 0u; }

// =====================================================================
extern "C" void kernel_launch(void* const* d_in, const int* in_sizes, int n_in,
                              void* d_out, int out_size)
{
    (void)in_sizes; (void)n_in; (void)out_size;
    const float* x   = (const float*)d_in[0];
    const float* W1f = (const float*)d_in[1];
    const float* U1f = (const float*)d_in[2];
    const float* b1f = (const float*)d_in[3];
    const float* W1b = (const float*)d_in[4];
    const float* U1b = (const float*)d_in[5];
    const float* b1b = (const float*)d_in[6];
    const float* W2f = (const float*)d_in[7];
    const float* U2f = (const float*)d_in[8];
    const float* b2f = (const float*)d_in[9];
    const float* W2b = (const float*)d_in[10];
    const float* U2b = (const float*)d_in[11];
    const float* b2b = (const float*)d_in[12];
    const float* Wd  = (const float*)d_in[13];
    const float* bd  = (const float*)d_in[14];
    float* out = (float*)d_out;

    float *Zf, *Zb, *h1, *h2, *xr;
    float *Wt1f, *Wt1b, *Wt2f, *Wt2b, *Wtd;
    cudaGetSymbolAddress((void**)&Zf, g_Zf);
    cudaGetSymbolAddress((void**)&Zb, g_Zb);
    cudaGetSymbolAddress((void**)&h1, g_h1);
    cudaGetSymbolAddress((void**)&h2, g_h2);
    cudaGetSymbolAddress((void**)&xr, g_xr);
    cudaGetSymbolAddress((void**)&Wt1f, g_Wt1f);
    cudaGetSymbolAddress((void**)&Wt1b, g_Wt1b);
    cudaGetSymbolAddress((void**)&Wt2f, g_Wt2f);
    cudaGetSymbolAddress((void**)&Wt2b, g_Wt2b);
    cudaGetSymbolAddress((void**)&Wtd, g_Wtd);

    const int GEMM_SMEM = 4 * ABUF * 4;
    cudaFuncSetAttribute(mma_gemm_kernel<0>, cudaFuncAttributeMaxDynamicSharedMemorySize, GEMM_SMEM);
    cudaFuncSetAttribute(mma_gemm_kernel<1>, cudaFuncAttributeMaxDynamicSharedMemorySize, GEMM_SMEM);
    cudaFuncSetAttribute(lstm_mma_kernel<0>, cudaFuncAttributeMaxDynamicSharedMemorySize, LSTM_SMEM);
    cudaFuncSetAttribute(lstm_mma_kernel<1>, cudaFuncAttributeMaxDynamicSharedMemorySize, LSTM_SMEM);

    dim3 blk(256);
    dim3 gZ(2048 / 128, 65536 / 128);
    dim3 gO(512 / 128, 65536 / 128);

    prep_all_kernel<<<dim3(2048, 6), 256>>>(x, xr, W1f, Wt1f, W1b, Wt1b,
                                            W2f, Wt2f, W2b, Wt2b, Wd, Wtd);
    // Z projections use SCATTER=1 ([t][b][4H] layout read by the LSTM)
    mma_gemm_kernel<1><<<gZ, blk, GEMM_SMEM>>>(xr, Wt1f, b1f, Zf, 512, 2048);
    mma_gemm_kernel<1><<<gZ, blk, GEMM_SMEM>>>(xr, Wt1b, b1b, Zb, 512, 2048);
    reset_bar_kernel<<<1, 1>>>();

    // layer-1 recurrence
    lstm_mma_kernel<1><<<128, 256, LSTM_SMEM>>>(Zf, Zb, U1f, U1b, h1);

    // layer-2 input projections (SCATTER=1)
    mma_gemm_kernel<1><<<gZ, blk, GEMM_SMEM>>>(h1, Wt2f, b2f, Zf, 1024, 2048);
    mma_gemm_kernel<1><<<gZ, blk, GEMM_SMEM>>>(h1, Wt2b, b2b, Zb, 1024, 2048);

    // layer-2 recurrence
    reset_bar_kernel<<<1, 1>>>();
    lstm_mma_kernel<0><<<128, 256, LSTM_SMEM>>>(Zf, Zb, U2f, U2b, h2);

    // dense head (single tf32 GEMM, row-major out): out = tf32(h1+h2) @ Wtd + bd
    add_round_kernel<<<(16777216 + 255) / 256, 256>>>(h1, h2, Zf, 16777216);
    mma_gemm_kernel<0><<<gO, blk, GEMM_SMEM>>>(Zf, Wtd, bd, out, 1024, 512);
}

// round 17
// speedup vs baseline: 1.4290x; 1.0232x over previous
#include <cuda_runtime.h>
#include <cuda_bf16.h>
#include <math.h>
#include <stdint.h>

#define TSTEPS 1024
#define BATCH  64
#define HID    512

// ---------------- scratch (static device allocations; no cudaMalloc) ----------------
__device__ float g_Zf[(size_t)TSTEPS * BATCH * 2048];   // Z fwd [t][b][4H]; later hsum
__device__ float g_Zb[(size_t)TSTEPS * BATCH * 2048];   // Z bwd [t][b][4H]
__device__ float g_h1[(size_t)BATCH * TSTEPS * 1024];   // layer1 out [b][t][2H] (tf32)
__device__ float g_h2[(size_t)BATCH * TSTEPS * 1024];   // layer2 out [b][t][2H] (fp32)
__device__ float g_xr[(size_t)BATCH * TSTEPS * 512];    // tf32-rounded x
// h state, bf16x2 packed: [dir][phase][kword(=col/2)][b]
__device__ uint32_t g_hstB[2][2][256 * 64];
__device__ unsigned int g_bar2[64];                     // per-dir barrier counters ([0],[32])

// transposed + tf32-rounded weights [N][K]
__device__ float g_Wt1f[2048 * 512];
__device__ float g_Wt1b[2048 * 512];
__device__ float g_Wt2f[2048 * 1024];
__device__ float g_Wt2b[2048 * 1024];
__device__ float g_Wtd [512 * 1024];

__device__ __forceinline__ float to_tf32(float v) {
    float r; asm("cvt.rna.tf32.f32 %0, %1;" : "=f"(r) : "f"(v)); return r;
}
__device__ __forceinline__ uint32_t smem_u32(const void* p) {
    uint32_t a;
    asm("{ .reg .u64 t; cvta.to.shared.u64 t, %1; cvt.u32.u64 %0, t; }" : "=r"(a) : "l"(p));
    return a;
}
__device__ __forceinline__ float fsigm(float x) { return 1.f / (1.f + __expf(-x)); }
__device__ __forceinline__ float ftanh(float x) {
    float e = __expf(2.f * x);
    return 1.f - __fdividef(2.f, e + 1.f);
}
__device__ __forceinline__ void cp16(uint32_t dst, const void* src) {
    asm volatile("cp.async.cg.shared.global [%0], [%1], 16;" :: "r"(dst), "l"(src));
}
__device__ __forceinline__ uint32_t pack_bf2(float a, float b) {
    __nv_bfloat16 ha = __float2bfloat16(a), hb = __float2bfloat16(b);
    return (uint32_t)__bfloat16_as_ushort(ha) | ((uint32_t)__bfloat16_as_ushort(hb) << 16);
}

// =====================================================================
//  Fused prep kernel: blockIdx.y selects task.
// =====================================================================
__global__ void prep_all_kernel(
    const float* __restrict__ x,   float* __restrict__ xr,
    const float* __restrict__ W1f, float* __restrict__ Wt1f,
    const float* __restrict__ W1b, float* __restrict__ Wt1b,
    const float* __restrict__ W2f, float* __restrict__ Wt2f,
    const float* __restrict__ W2b, float* __restrict__ Wt2b,
    const float* __restrict__ Wd,  float* __restrict__ Wtd)
{
    const int task = blockIdx.y;
    if (task == 0) {
        const int n4 = 8388608;
        for (int i = blockIdx.x * 256 + threadIdx.x; i < n4; i += 2048 * 256) {
            float4 v = ((const float4*)x)[i];
            ((float4*)xr)[i] = make_float4(to_tf32(v.x), to_tf32(v.y),
                                           to_tf32(v.z), to_tf32(v.w));
        }
        return;
    }
    const float* W; float* Wt; int K, N;
    switch (task) {
        case 1: W = W1f; Wt = Wt1f; K = 512;  N = 2048; break;
        case 2: W = W1b; Wt = Wt1b; K = 512;  N = 2048; break;
        case 3: W = W2f; Wt = Wt2f; K = 1024; N = 2048; break;
        case 4: W = W2b; Wt = Wt2b; K = 1024; N = 2048; break;
        default: W = Wd; Wt = Wtd; K = 1024; N = 512; break;
    }
    const int nkb = K / 32;
    const int total = nkb * (N / 32);
    const int bx = blockIdx.x;
    if (bx >= total) return;
    __shared__ float tile[32][33];
    const int kb = (bx % nkb) * 32, nb = (bx / nkb) * 32;
    const int tx = threadIdx.x & 31, ty = threadIdx.x >> 5;
#pragma unroll
    for (int i = ty; i < 32; i += 8)
        tile[i][tx] = W[(size_t)(kb + i) * N + nb + tx];
    __syncthreads();
#pragma unroll
    for (int i = ty; i < 32; i += 8)
        Wt[(size_t)(nb + i) * K + kb + tx] = to_tf32(tile[tx][i]);
}

// hsum = tf32(h1 + h2)
__global__ void add_round_kernel(const float* __restrict__ a, const float* __restrict__ b,
                                 float* __restrict__ o, int n4)
{
    int i = blockIdx.x * blockDim.x + threadIdx.x;
    if (i < n4) {
        float4 va = ((const float4*)a)[i];
        float4 vb = ((const float4*)b)[i];
        ((float4*)o)[i] = make_float4(to_tf32(va.x + vb.x), to_tf32(va.y + vb.y),
                                      to_tf32(va.z + vb.z), to_tf32(va.w + vb.w));
    }
}

// =====================================================================
//  TF32 mma.sync GEMM (validated R4):  C = A @ Bt^T (+bias)
//  SCATTER 1: out layout [t][b][N]   SCATTER 0: row-major
// =====================================================================
#define ABUF 4608   // 128*36 floats per buffer

template <int SCATTER>
__global__ void __launch_bounds__(256, 2)
mma_gemm_kernel(const float* __restrict__ A, const float* __restrict__ Bt,
                const float* __restrict__ bias, float* __restrict__ C, int K, int N)
{
    extern __shared__ float smf[];
    const int tid = threadIdx.x;
    const int wid = tid >> 5, lane = tid & 31;
    const int warp_m = wid & 1, warp_n = wid >> 1;
    const size_t rowBase = (size_t)blockIdx.y * 128;
    const size_t colBase = (size_t)blockIdx.x * 128;
    const uint32_t smbase = smem_u32(smf);
    const int NS = K >> 5;

    float acc[4][4][4];
#pragma unroll
    for (int mi = 0; mi < 4; ++mi)
#pragma unroll
        for (int ni = 0; ni < 4; ++ni)
#pragma unroll
            for (int r = 0; r < 4; ++r) acc[mi][ni][r] = 0.f;

    auto cp_tile = [&](int s, int p) {
        const int kt = s << 5;
#pragma unroll
        for (int i = 0; i < 4; ++i) {
            int idx = i * 256 + tid;
            int row = idx >> 3, f4 = idx & 7;
            uint32_t da = smbase + (uint32_t)((p * ABUF + row * 36 + f4 * 4) << 2);
            cp16(da, A + (rowBase + row) * K + kt + f4 * 4);
            uint32_t db = smbase + (uint32_t)(((2 * ABUF) + p * ABUF + row * 36 + f4 * 4) << 2);
            cp16(db, Bt + (colBase + row) * K + kt + f4 * 4);
        }
        asm volatile("cp.async.commit_group;");
    };

    cp_tile(0, 0);
    cp_tile(1, 1);

    const int g = lane >> 2, c = lane & 3;
    const int ar0 = warp_m * 64 + g;
    const int bn0 = warp_n * 32 + g;

    for (int s = 0; s < NS; ++s) {
        const int p = s & 1;
        if (s + 1 < NS) asm volatile("cp.async.wait_group 1;");
        else            asm volatile("cp.async.wait_group 0;");
        __syncthreads();

        const float* Ab = smf + p * ABUF;
        const float* Bb = smf + 2 * ABUF + p * ABUF;

#pragma unroll
        for (int k8 = 0; k8 < 4; ++k8) {
            const int kc = k8 * 8 + c;
            uint32_t a[4][4], b[4][2];
#pragma unroll
            for (int mi = 0; mi < 4; ++mi) {
                const float* base = Ab + (ar0 + mi * 16) * 36 + kc;
                a[mi][0] = __float_as_uint(base[0]);
                a[mi][1] = __float_as_uint(base[8 * 36]);
                a[mi][2] = __float_as_uint(base[4]);
                a[mi][3] = __float_as_uint(base[8 * 36 + 4]);
            }
#pragma unroll
            for (int ni = 0; ni < 4; ++ni) {
                const float* base = Bb + (bn0 + ni * 8) * 36 + kc;
                b[ni][0] = __float_as_uint(base[0]);
                b[ni][1] = __float_as_uint(base[4]);
            }
#pragma unroll
            for (int mi = 0; mi < 4; ++mi)
#pragma unroll
                for (int ni = 0; ni < 4; ++ni)
                    asm volatile(
                        "mma.sync.aligned.m16n8k8.row.col.f32.tf32.tf32.f32 "
                        "{%0,%1,%2,%3}, {%4,%5,%6,%7}, {%8,%9}, {%0,%1,%2,%3};"
                        : "+f"(acc[mi][ni][0]), "+f"(acc[mi][ni][1]),
                          "+f"(acc[mi][ni][2]), "+f"(acc[mi][ni][3])
                        : "r"(a[mi][0]), "r"(a[mi][1]), "r"(a[mi][2]), "r"(a[mi][3]),
                          "r"(b[ni][0]), "r"(b[ni][1]));
        }
        __syncthreads();
        if (s + 2 < NS) cp_tile(s + 2, p);
    }

    const int c2 = (lane & 3) * 2;
#pragma unroll
    for (int mi = 0; mi < 4; ++mi) {
        size_t r0 = rowBase + warp_m * 64 + mi * 16 + g;
        size_t r8 = r0 + 8;
        size_t off0, off8;
        if (SCATTER) {
            off0 = (((r0 & 1023) << 6) + (r0 >> 10)) * (size_t)N;
            off8 = (((r8 & 1023) << 6) + (r8 >> 10)) * (size_t)N;
        } else {
            off0 = r0 * (size_t)N;
            off8 = r8 * (size_t)N;
        }
#pragma unroll
        for (int ni = 0; ni < 4; ++ni) {
            size_t col = colBase + warp_n * 32 + ni * 8 + c2;
            float2 bv = *(const float2*)&bias[col];
            float2 v0 = make_float2(acc[mi][ni][0] + bv.x, acc[mi][ni][1] + bv.y);
            float2 v1 = make_float2(acc[mi][ni][2] + bv.x, acc[mi][ni][3] + bv.y);
            *(float2*)&C[off0 + col] = v0;
            *(float2*)&C[off8 + col] = v1;
        }
    }
}

// =====================================================================
//  Persistent bidirectional LSTM layer — bf16 tensor-core recurrence.
//  R17: barrier via red.release.gpu + ld.acquire.gpu (grid.sync pattern)
//  — removes the per-step gpu-scope MEMBAR + CCTL.IVALL L1 flush that
//  __threadfence() implied. Producer/consumer path is pure L2 (__stcg /
//  cp.async.cg), so release/acquire ordering suffices.
// =====================================================================
__device__ __forceinline__ void bar_arrive(int dir)
{
    __syncthreads();
    if (threadIdx.x == 0) {
        unsigned int* p = &g_bar2[dir * 32];
        asm volatile("red.release.gpu.global.add.u32 [%0], %1;"
                     :: "l"(p), "r"(1u) : "memory");
    }
}
__device__ __forceinline__ void bar_wait(int dir, unsigned int target)
{
    if (threadIdx.x == 0) {
        unsigned int* p = &g_bar2[dir * 32];
        unsigned int v;
        do {
            asm volatile("ld.acquire.gpu.global.u32 %0, [%1];"
                         : "=r"(v) : "l"(p) : "memory");
        } while (v < target);
    }
    __syncthreads();
}

#define LSTM_SMEM ((4 * 64 * 72 + 4 * 32 * 66) * 4)   // 107,520 B

template <int ROUND>
__global__ void __launch_bounds__(256, 1)
lstm_mma_kernel(const float* __restrict__ Zf, const float* __restrict__ Zb,
                const float* __restrict__ Uf, const float* __restrict__ Ub,
                float* __restrict__ hout)
{
    extern __shared__ float sm[];
    uint32_t* hsw = (uint32_t*)sm;      // [4 ks][64 kw][72] bf16x2 words
    float* zred = sm + 18432;           // [4 ks][32 l][66]

    const int tid = threadIdx.x;
    const int w = tid >> 5, lane = tid & 31;
    const int g = lane >> 2, c = lane & 3;
    const int ks = w >> 1, mg = w & 1;
    const int dir = blockIdx.x >> 6;
    const int jb  = blockIdx.x & 63;
    const float* U = dir ? Ub : Uf;
    const float* Z = dir ? Zb : Zf;
    uint32_t* hstB0 = &g_hstB[dir][0][0];
    uint32_t* hstB1 = &g_hstB[dir][1][0];

    // ---- one-time: U A-fragments (bf16 hi+lo split), registers ----
    uint32_t uhi[8][4], ulo[8][4];
    {
        const int l0 = mg * 16 + g, l1 = l0 + 8;
        const int gc0 = (l0 >> 3) * 512 + jb * 8 + (l0 & 7);
        const int gc1 = (l1 >> 3) * 512 + jb * 8 + (l1 & 7);
#pragma unroll
        for (int kk = 0; kk < 8; ++kk) {
            int kb = ks * 128 + kk * 16;
#pragma unroll
            for (int r = 0; r < 4; ++r) {
                int k0 = kb + 2 * c + ((r >> 1) ? 8 : 0);
                int gc = (r & 1) ? gc1 : gc0;
                float v0 = U[(size_t)k0 * 2048 + gc];
                float v1 = U[(size_t)(k0 + 1) * 2048 + gc];
                __nv_bfloat16 h0 = __float2bfloat16(v0);
                __nv_bfloat16 h1 = __float2bfloat16(v1);
                uhi[kk][r] = (uint32_t)__bfloat16_as_ushort(h0) |
                             ((uint32_t)__bfloat16_as_ushort(h1) << 16);
                ulo[kk][r] = pack_bf2(v0 - __bfloat162float(h0),
                                      v1 - __bfloat162float(h1));
            }
        }
    }

    // zero own kwords of phase-0 state
    hstB0[jb * 256 + tid] = 0u;
    bar_arrive(dir);
    bar_wait(dir, 64u);

    const int eb = tid >> 2;
    const int q0 = (tid & 3) * 2;
    float cst0 = 0.f, cst1 = 0.f;
    const int pt = tid & 63;
    uint32_t* hsP = hsw + ks * 4608;
    const uint32_t hsPb = smem_u32(hsP);

    // prologue Z prefetch for s=0
    float2 zi2, zf2, zg2, zo2;
    {
        int t0 = dir ? (TSTEPS - 1) : 0;
        const float* Zt = Z + ((size_t)t0 * 64 + eb) * 2048 + jb * 8 + q0;
        zi2 = *(const float2*)(Zt + 0);
        zf2 = *(const float2*)(Zt + 512);
        zg2 = *(const float2*)(Zt + 1024);
        zo2 = *(const float2*)(Zt + 1536);
    }

    for (int s = 0; s < TSTEPS; ++s) {
        const int t = dir ? (TSTEPS - 1 - s) : s;
        const uint32_t* hsrc = (s & 1) ? hstB1 : hstB0;
        uint32_t* hdst = (s & 1) ? hstB0 : hstB1;

        // ---- stage pair's K-slice via cp.async: [kw][b] words, 16 KB/pair ----
        {
            const float4* src = (const float4*)(hsrc + ks * 4096);
#pragma unroll
            for (int i = 0; i < 16; ++i) {
                int idx = i * 64 + pt;
                int kl = idx >> 4, q4 = idx & 15;
                cp16(hsPb + (uint32_t)((kl * 72 + q4 * 4) << 2), src + idx);
            }
            asm volatile("cp.async.commit_group;");
            asm volatile("cp.async.wait_group 0;");
        }
        asm volatile("bar.sync %0, %1;" :: "r"(1 + ks), "r"(64) : "memory");

        // ---- bf16 MMA: z[l][b] over k in [ks*128,+128), 8 k16-chunks ----
        float acc[8][4];
#pragma unroll
        for (int nt = 0; nt < 8; ++nt)
#pragma unroll
            for (int r = 0; r < 4; ++r) acc[nt][r] = 0.f;

#pragma unroll
        for (int kk = 0; kk < 8; ++kk) {
            uint32_t ah0 = uhi[kk][0], ah1 = uhi[kk][1], ah2 = uhi[kk][2], ah3 = uhi[kk][3];
            uint32_t al0 = ulo[kk][0], al1 = ulo[kk][1], al2 = ulo[kk][2], al3 = ulo[kk][3];
            const uint32_t* rowA = hsP + (kk * 8 + c) * 72;
            const uint32_t* rowB = rowA + 4 * 72;
#pragma unroll
            for (int nt = 0; nt < 8; ++nt) {
                uint32_t b0 = rowA[nt * 8 + g];
                uint32_t b1 = rowB[nt * 8 + g];
                asm volatile(
                    "mma.sync.aligned.m16n8k16.row.col.f32.bf16.bf16.f32 "
                    "{%0,%1,%2,%3}, {%4,%5,%6,%7}, {%8,%9}, {%0,%1,%2,%3};"
                    : "+f"(acc[nt][0]), "+f"(acc[nt][1]), "+f"(acc[nt][2]), "+f"(acc[nt][3])
                    : "r"(ah0), "r"(ah1), "r"(ah2), "r"(ah3),
                      "r"(b0), "r"(b1));
                asm volatile(
                    "mma.sync.aligned.m16n8k16.row.col.f32.bf16.bf16.f32 "
                    "{%0,%1,%2,%3}, {%4,%5,%6,%7}, {%8,%9}, {%0,%1,%2,%3};"
                    : "+f"(acc[nt][0]), "+f"(acc[nt][1]), "+f"(acc[nt][2]), "+f"(acc[nt][3])
                    : "r"(al0), "r"(al1), "r"(al2), "r"(al3),
                      "r"(b0), "r"(b1));
            }
        }

        // ---- store partials: zred[ks][l][b] ----
#pragma unroll
        for (int nt = 0; nt < 8; ++nt) {
            int l0 = mg * 16 + g;
            int n0 = nt * 8 + c * 2;
            *(float2*)&zred[(ks * 32 + l0) * 66 + n0]     = make_float2(acc[nt][0], acc[nt][1]);
            *(float2*)&zred[(ks * 32 + l0 + 8) * 66 + n0] = make_float2(acc[nt][2], acc[nt][3]);
        }
        __syncthreads();

        // ---- gate epilogue ----
        float hh0, hh1;
        {
            float vi0 = zi2.x, vi1 = zi2.y, vf0 = zf2.x, vf1 = zf2.y;
            float vg0 = zg2.x, vg1 = zg2.y, vo0 = zo2.x, vo1 = zo2.y;
#pragma unroll
            for (int k = 0; k < 4; ++k) {
                vi0 += zred[(k * 32 + q0)      * 66 + eb];
                vi1 += zred[(k * 32 + q0 + 1)  * 66 + eb];
                vf0 += zred[(k * 32 + 8 + q0)  * 66 + eb];
                vf1 += zred[(k * 32 + 9 + q0)  * 66 + eb];
                vg0 += zred[(k * 32 + 16 + q0) * 66 + eb];
                vg1 += zred[(k * 32 + 17 + q0) * 66 + eb];
                vo0 += zred[(k * 32 + 24 + q0) * 66 + eb];
                vo1 += zred[(k * 32 + 25 + q0) * 66 + eb];
            }
            float ig0 = fsigm(vi0), ig1 = fsigm(vi1);
            float fg0 = fsigm(vf0), fg1 = fsigm(vf1);
            float gg0 = ftanh(vg0), gg1 = ftanh(vg1);
            float og0 = fsigm(vo0), og1 = fsigm(vo1);
            cst0 = fg0 * cst0 + ig0 * gg0;
            cst1 = fg1 * cst1 + ig1 * gg1;
            hh0 = og0 * ftanh(cst0);
            hh1 = og1 * ftanh(cst1);

            __stcg(&hdst[(jb * 4 + (q0 >> 1)) * 64 + eb], pack_bf2(hh0, hh1));
        }

        bar_arrive(dir);

        size_t ho = ((size_t)eb * 1024 + t) * 1024 + dir * 512 + jb * 8 + q0;
        if (ROUND) {
            hout[ho]     = to_tf32(hh0);
            hout[ho + 1] = to_tf32(hh1);
        } else {
            hout[ho]     = hh0;
            hout[ho + 1] = hh1;
        }

        if (s + 1 < TSTEPS) {
            int tn = dir ? (TSTEPS - 2 - s) : (s + 1);
            const float* Zt = Z + ((size_t)tn * 64 + eb) * 2048 + jb * 8 + q0;
            zi2 = *(const float2*)(Zt + 0);
            zf2 = *(const float2*)(Zt + 512);
            zg2 = *(const float2*)(Zt + 1024);
            zo2 = *(const float2*)(Zt + 1536);
            bar_wait(dir, 64u * (unsigned)(s + 2));
        }
    }
}

__global__ void reset_bar_kernel() { g_bar2[0] = 0u; g_bar2[32] = 0u; }

// =====================================================================
extern "C" void kernel_launch(void* const* d_in, const int* in_sizes, int n_in,
                              void* d_out, int out_size)
{
    (void)in_sizes; (void)n_in; (void)out_size;
    const float* x   = (const float*)d_in[0];
    const float* W1f = (const float*)d_in[1];
    const float* U1f = (const float*)d_in[2];
    const float* b1f = (const float*)d_in[3];
    const float* W1b = (const float*)d_in[4];
    const float* U1b = (const float*)d_in[5];
    const float* b1b = (const float*)d_in[6];
    const float* W2f = (const float*)d_in[7];
    const float* U2f = (const float*)d_in[8];
    const float* b2f = (const float*)d_in[9];
    const float* W2b = (const float*)d_in[10];
    const float* U2b = (const float*)d_in[11];
    const float* b2b = (const float*)d_in[12];
    const float* Wd  = (const float*)d_in[13];
    const float* bd  = (const float*)d_in[14];
    float* out = (float*)d_out;

    float *Zf, *Zb, *h1, *h2, *xr;
    float *Wt1f, *Wt1b, *Wt2f, *Wt2b, *Wtd;
    cudaGetSymbolAddress((void**)&Zf, g_Zf);
    cudaGetSymbolAddress((void**)&Zb, g_Zb);
    cudaGetSymbolAddress((void**)&h1, g_h1);
    cudaGetSymbolAddress((void**)&h2, g_h2);
    cudaGetSymbolAddress((void**)&xr, g_xr);
    cudaGetSymbolAddress((void**)&Wt1f, g_Wt1f);
    cudaGetSymbolAddress((void**)&Wt1b, g_Wt1b);
    cudaGetSymbolAddress((void**)&Wt2f, g_Wt2f);
    cudaGetSymbolAddress((void**)&Wt2b, g_Wt2b);
    cudaGetSymbolAddress((void**)&Wtd, g_Wtd);

    const int GEMM_SMEM = 4 * ABUF * 4;
    cudaFuncSetAttribute(mma_gemm_kernel<0>, cudaFuncAttributeMaxDynamicSharedMemorySize, GEMM_SMEM);
    cudaFuncSetAttribute(mma_gemm_kernel<1>, cudaFuncAttributeMaxDynamicSharedMemorySize, GEMM_SMEM);
    cudaFuncSetAttribute(lstm_mma_kernel<0>, cudaFuncAttributeMaxDynamicSharedMemorySize, LSTM_SMEM);
    cudaFuncSetAttribute(lstm_mma_kernel<1>, cudaFuncAttributeMaxDynamicSharedMemorySize, LSTM_SMEM);

    dim3 blk(256);
    dim3 gZ(2048 / 128, 65536 / 128);
    dim3 gO(512 / 128, 65536 / 128);

    prep_all_kernel<<<dim3(2048, 6), 256>>>(x, xr, W1f, Wt1f, W1b, Wt1b,
                                            W2f, Wt2f, W2b, Wt2b, Wd, Wtd);
    // Z projections use SCATTER=1 ([t][b][4H] layout read by the LSTM)
    mma_gemm_kernel<1><<<gZ, blk, GEMM_SMEM>>>(xr, Wt1f, b1f, Zf, 512, 2048);
    mma_gemm_kernel<1><<<gZ, blk, GEMM_SMEM>>>(xr, Wt1b, b1b, Zb, 512, 2048);
    reset_bar_kernel<<<1, 1>>>();

    // layer-1 recurrence
    lstm_mma_kernel<1><<<128, 256, LSTM_SMEM>>>(Zf, Zb, U1f, U1b, h1);

    // layer-2 input projections (SCATTER=1)
    mma_gemm_kernel<1><<<gZ, blk, GEMM_SMEM>>>(h1, Wt2f, b2f, Zf, 1024, 2048);
    mma_gemm_kernel<1><<<gZ, blk, GEMM_SMEM>>>(h1, Wt2b, b2b, Zb, 1024, 2048);

    // layer-2 recurrence
    reset_bar_kernel<<<1, 1>>>();
    lstm_mma_kernel<0><<<128, 256, LSTM_SMEM>>>(Zf, Zb, U2f, U2b, h2);

    // dense head (single tf32 GEMM, row-major out): out = tf32(h1+h2) @ Wtd + bd
    add_round_kernel<<<(16777216 + 255) / 256, 256>>>(h1, h2, Zf, 16777216);
    mma_gemm_kernel<0><<<gO, blk, GEMM_SMEM>>>(Zf, Wtd, bd, out, 1024, 512);
}